// round 12
// baseline (speedup 1.0000x reference)
#include <cuda_runtime.h>
#include <math.h>
#include <stddef.h>

#define BB 4
#define NN 1024
#define DD 1024
#define EE 32
#define HH 4096
#define LN_EPS 1e-5f
#define PS_EPS 1e-9f

// ---------------- scratch (device globals) ----------------
__device__ __align__(16) float g_logitsT[BB * EE * NN];   // [b][e][n]
__device__ __align__(16) float g_cw[BB * NN * EE];        // combine weights [b][n][e]
__device__ __align__(16) float2 g_minv[BB * EE];          // (max, 1/sum) per (b,e)
__device__ float g_cwterm[BB * NN];
__device__ float g_cwdiag[BB * EE];
__device__ float g_dwterm[BB * EE];
__device__ __align__(16) float g_slots_part[16][BB * EE * DD];
__device__ __align__(16) float g_slots[BB * EE * DD];
__device__ int g_cnt[128];   // [0..31] slots, [32..35] logits-batch, [36] scalars, [64..95] w2
__device__ __align__(16) float g_h1p[8][EE * BB * HH];    // pre-gelu partials (k-split 8)
__device__ __align__(16) float g_eo_part[32][BB * EE * DD];
__device__ __align__(16) float g_eo[BB * EE * DD];

__device__ __forceinline__ float fold_dq(float v) {
    v += __shfl_xor_sync(0xffffffffu, v, 8);
    v += __shfl_xor_sync(0xffffffffu, v, 16);
    return v;
}

// ---------------- K1: logits (qnorm + combine softmax + dstats + scalars fused) ----------------
// grid (nt=32, b=4) = 128 blocks, 256 threads.
__global__ __launch_bounds__(256) void k_logits(
    const float* __restrict__ x, const float* __restrict__ kg,
    const float* __restrict__ kb,
    const float* __restrict__ phi, const float* __restrict__ qg,
    const float* __restrict__ qb, const float* __restrict__ lng,
    const float* __restrict__ lnb, const float* __restrict__ scale_p,
    float* __restrict__ out) {
    int b = blockIdx.y;
    int n0 = blockIdx.x * 32;
    int t = threadIdx.x;
    int eq = t >> 5;         // 0..7
    int dq = (t >> 3) & 3;   // 0..3
    int nq = t & 7;          // 0..7

    __shared__ float xsT[128][36];  // [d within chunk][n]
    __shared__ float qsT[128][36];  // [d within chunk][e]
    __shared__ float cs2[32][33];   // this tile's logits [local n][e]
    __shared__ float sm_mean[EE], sm_rstd[EE];
    __shared__ bool sdo, sdo2;

    int w = t >> 5, l = t & 31;

    // ---- Phase A: per-expert LN stats (one-pass) ----
#pragma unroll
    for (int ei = 0; ei < 4; ei++) {
        int e = w + ei * 8;
        float s1 = 0.f, s2 = 0.f;
#pragma unroll 4
        for (int k = 0; k < 32; k++) {
            int d = l + 32 * k;
            float v = phi[e * DD + d] * qg[d] + qb[d];
            s1 += v; s2 += v * v;
        }
#pragma unroll
        for (int o = 16; o; o >>= 1) {
            s1 += __shfl_xor_sync(0xffffffffu, s1, o);
            s2 += __shfl_xor_sync(0xffffffffu, s2, o);
        }
        if (l == 0) {
            float mean = s1 * (1.f / DD);
            float var = s2 * (1.f / DD) - mean * mean;
            sm_mean[e] = mean;
            sm_rstd[e] = rsqrtf(var + LN_EPS);
        }
    }
    float sc = *scale_p;

    int dseg = (w & 3) * 32;        // d-segment within 128-chunk
    int half = (w >> 2) * 16;       // n-half / e-half

    float4 aN0 = make_float4(0.f, 0.f, 0.f, 0.f), aN1 = aN0, aN2 = aN0, aN3 = aN0;

    for (int c = 0; c < 8; c++) {
        int dd0 = dseg + l;              // 0..127
        int dglob = c * 128 + dd0;
        float kgv = kg[dglob], kbv = kb[dglob];
        float qgv = qg[dglob], qbv = qb[dglob];
        float lngv = lng[dglob], lnbv = lnb[dglob];
        __syncthreads();
#pragma unroll
        for (int i = 0; i < 16; i++) {
            int n = half + i;
            xsT[dd0][n] = x[((size_t)(b * NN) + n0 + n) * DD + dglob] * kgv + kbv;
            float v = phi[n * DD + dglob] * qgv + qbv;   // n doubles as expert row
            qsT[dd0][n] = ((v - sm_mean[n]) * sm_rstd[n] * lngv + lnbv) * sc;
        }
        __syncthreads();
#pragma unroll
        for (int k = 0; k < 32; k++) {
            int dd = dq * 32 + k;
            float4 xv = *reinterpret_cast<const float4*>(&xsT[dd][nq * 4]);
            float4 qv = *reinterpret_cast<const float4*>(&qsT[dd][eq * 4]);
            aN0.x += xv.x * qv.x; aN0.y += xv.x * qv.y; aN0.z += xv.x * qv.z; aN0.w += xv.x * qv.w;
            aN1.x += xv.y * qv.x; aN1.y += xv.y * qv.y; aN1.z += xv.y * qv.z; aN1.w += xv.y * qv.w;
            aN2.x += xv.z * qv.x; aN2.y += xv.z * qv.y; aN2.z += xv.z * qv.z; aN2.w += xv.z * qv.w;
            aN3.x += xv.w * qv.x; aN3.y += xv.w * qv.y; aN3.z += xv.w * qv.z; aN3.w += xv.w * qv.w;
        }
    }

    aN0.x = fold_dq(aN0.x); aN0.y = fold_dq(aN0.y); aN0.z = fold_dq(aN0.z); aN0.w = fold_dq(aN0.w);
    aN1.x = fold_dq(aN1.x); aN1.y = fold_dq(aN1.y); aN1.z = fold_dq(aN1.z); aN1.w = fold_dq(aN1.w);
    aN2.x = fold_dq(aN2.x); aN2.y = fold_dq(aN2.y); aN2.z = fold_dq(aN2.z); aN2.w = fold_dq(aN2.w);
    aN3.x = fold_dq(aN3.x); aN3.y = fold_dq(aN3.y); aN3.z = fold_dq(aN3.z); aN3.w = fold_dq(aN3.w);

    if (dq == 0) {
        float4 accs[4] = {aN0, aN1, aN2, aN3};
#pragma unroll
        for (int i = 0; i < 4; i++) {
            int lr = nq * 4 + i;          // local row 0..31
            int n = n0 + lr;
            cs2[lr][eq * 4 + 0] = accs[i].x;
            cs2[lr][eq * 4 + 1] = accs[i].y;
            cs2[lr][eq * 4 + 2] = accs[i].z;
            cs2[lr][eq * 4 + 3] = accs[i].w;
            g_logitsT[((size_t)(b * EE) + eq * 4 + 0) * NN + n] = accs[i].x;
            g_logitsT[((size_t)(b * EE) + eq * 4 + 1) * NN + n] = accs[i].y;
            g_logitsT[((size_t)(b * EE) + eq * 4 + 2) * NN + n] = accs[i].z;
            g_logitsT[((size_t)(b * EE) + eq * 4 + 3) * NN + n] = accs[i].w;
        }
    }
    __syncthreads();

    // ---- fused combine softmax over E for this tile's 32 rows ----
    // warp w handles rows w*4 .. w*4+3; lane group j = l&7 handles e = j*4..j*4+3
    {
        int r = w * 4 + (l >> 3);       // local row
        int j = l & 7;                   // e-quad id (lane bits 0..2)
        float cv[4];
#pragma unroll
        for (int i = 0; i < 4; i++) cv[i] = cs2[r][j * 4 + i];

        float m = fmaxf(fmaxf(cv[0], cv[1]), fmaxf(cv[2], cv[3]));
        m = fmaxf(m, __shfl_xor_sync(0xffffffffu, m, 1));
        m = fmaxf(m, __shfl_xor_sync(0xffffffffu, m, 2));
        m = fmaxf(m, __shfl_xor_sync(0xffffffffu, m, 4));

        float ex[4], s = 0.f;
#pragma unroll
        for (int i = 0; i < 4; i++) { ex[i] = expf(cv[i] - m); s += ex[i]; }
        s += __shfl_xor_sync(0xffffffffu, s, 1);
        s += __shfl_xor_sync(0xffffffffu, s, 2);
        s += __shfl_xor_sync(0xffffffffu, s, 4);
        float inv = 1.f / s;

        float cw[4], sq = 0.f, scw = 0.f;
#pragma unroll
        for (int i = 0; i < 4; i++) { cw[i] = ex[i] * inv; sq += cw[i] * cw[i]; scw += cw[i]; }
        sq += __shfl_xor_sync(0xffffffffu, sq, 1);
        sq += __shfl_xor_sync(0xffffffffu, sq, 2);
        sq += __shfl_xor_sync(0xffffffffu, sq, 4);
        scw += __shfl_xor_sync(0xffffffffu, scw, 1);
        scw += __shfl_xor_sync(0xffffffffu, scw, 2);
        scw += __shfl_xor_sync(0xffffffffu, scw, 4);

        int bn = b * NN + n0 + r;
        *reinterpret_cast<float4*>(&g_cw[(size_t)bn * EE + j * 4]) =
            make_float4(cw[0], cw[1], cw[2], cw[3]);

        float rs = rsqrtf(sq + PS_EPS);
        float rows = scw * rs;
        int n = n0 + r;
        if (j == 0) g_cwterm[bn] = rows * rows;
        if (n < EE && j == (n >> 2))
            g_cwdiag[b * EE + n] = cw[n & 3] * rs * rows;
    }

    // ---- last-block dstats for this batch (32 arrivals) ----
    __threadfence();
    __syncthreads();
    if (t == 0) sdo = (atomicAdd(&g_cnt[32 + b], 1) == 31);
    __syncthreads();
    if (sdo) {
        if (t == 0) g_cnt[32 + b] = 0;   // self-reset
#pragma unroll
        for (int ei = 0; ei < 4; ei++) {
            int e = w * 4 + ei;
            const float* L = g_logitsT + ((size_t)(b * EE) + e) * NN;
            float m = -1e30f;
#pragma unroll 4
            for (int k = 0; k < 32; k++) m = fmaxf(m, L[k * 32 + l]);
#pragma unroll
            for (int o = 16; o; o >>= 1) m = fmaxf(m, __shfl_xor_sync(0xffffffffu, m, o));
            float s1 = 0.f, s2 = 0.f;
#pragma unroll 4
            for (int k = 0; k < 32; k++) {
                float ex = expf(L[k * 32 + l] - m);
                s1 += ex; s2 += ex * ex;
            }
#pragma unroll
            for (int o = 16; o; o >>= 1) {
                s1 += __shfl_xor_sync(0xffffffffu, s1, o);
                s2 += __shfl_xor_sync(0xffffffffu, s2, o);
            }
            if (l == 0) {
                float inv = 1.f / s1;
                g_minv[b * EE + e] = make_float2(m, inv);
                float wsq = s2 * inv * inv;
                float rs = rsqrtf(wsq + PS_EPS);
                float rn = (s1 * inv) * rs;
                g_dwterm[b * EE + e] = rn * rn;
            }
        }

        // ---- scalar metrics: last of the 4 batch-last blocks ----
        __threadfence();
        __syncthreads();
        if (t == 0) sdo2 = (atomicAdd(&g_cnt[36], 1) == 3);
        __syncthreads();
        if (sdo2) {
            __shared__ float red[256];
            if (t == 0) g_cnt[36] = 0;   // self-reset
            float vv;

            vv = 0.f; for (int i = t; i < BB * NN; i += 256) vv += g_cwterm[i];
            red[t] = vv; __syncthreads();
            for (int st = 128; st > 0; st >>= 1) { if (t < st) red[t] += red[t + st]; __syncthreads(); }
            float sumA = red[0]; __syncthreads();

            vv = 0.f; for (int i = t; i < BB * EE; i += 256) vv += g_cwdiag[i];
            red[t] = vv; __syncthreads();
            for (int st = 128; st > 0; st >>= 1) { if (t < st) red[t] += red[t + st]; __syncthreads(); }
            float sumAd = red[0]; __syncthreads();

            vv = 0.f; for (int i = t; i < BB * EE; i += 256) vv += g_dwterm[i];
            red[t] = vv; __syncthreads();
            for (int st = 128; st > 0; st >>= 1) { if (t < st) red[t] += red[t + st]; __syncthreads(); }
            float sumB = red[0]; __syncthreads();

            vv = (t < BB) ? g_dwterm[t * EE] : 0.f;
            red[t] = vv; __syncthreads();
            for (int st = 128; st > 0; st >>= 1) { if (t < st) red[t] += red[t + st]; __syncthreads(); }
            float sumB0 = red[0];

            if (t == 0) {
                out[(size_t)BB * NN * DD]     = (sumA - sumAd) / (float)(BB * (size_t)NN * (NN - 1));
                out[(size_t)BB * NN * DD + 1] = (sumB - sumB0) / (float)(BB * EE * (EE - 1));
            }
        }
    }
}

// ---------------- K2: slots partials + fused last-block reduction ----------------
// grid (dt=8, ns=16, b=4) = 512 blocks; thread: 4e x 4d (float4), 16 accs
__global__ __launch_bounds__(256) void k_slots(const float* __restrict__ x) {
    int dt = blockIdx.x;
    int ns = blockIdx.y;
    int b = blockIdx.z;
    int t = threadIdx.x;
    int td = t & 31;   // d-quad
    int te = t >> 5;   // 0..7 -> experts te*4..te*4+3
    int d0 = dt * 128;
    int n0 = ns * 64;

    __shared__ float4 xs4[32][32];   // [nn][d-quad], 16 KB
    __shared__ float dwsT[32][33];   // [e][nn]
    __shared__ bool sred;

    float4 a0 = make_float4(0.f, 0.f, 0.f, 0.f), a1 = a0, a2 = a0, a3 = a0;

    for (int c = 0; c < 2; c++) {
        int nc = n0 + c * 32;
        __syncthreads();
        for (int i = t; i < 1024; i += 256) {
            int row = i >> 5, q = i & 31;
            xs4[row][q] = *reinterpret_cast<const float4*>(
                x + ((size_t)(b * NN) + nc + row) * DD + d0 + q * 4);
        }
        for (int i = t; i < 1024; i += 256) {
            int e = i >> 5, nn = i & 31;
            float2 mi = g_minv[b * EE + e];
            float lv = g_logitsT[((size_t)(b * EE) + e) * NN + nc + nn];
            dwsT[e][nn] = expf(lv - mi.x) * mi.y;
        }
        __syncthreads();
#pragma unroll
        for (int k = 0; k < 32; k++) {
            float4 xv = xs4[k][td];
            float w0 = dwsT[te * 4 + 0][k];
            float w1 = dwsT[te * 4 + 1][k];
            float w2 = dwsT[te * 4 + 2][k];
            float w3 = dwsT[te * 4 + 3][k];
            a0.x += w0 * xv.x; a0.y += w0 * xv.y; a0.z += w0 * xv.z; a0.w += w0 * xv.w;
            a1.x += w1 * xv.x; a1.y += w1 * xv.y; a1.z += w1 * xv.z; a1.w += w1 * xv.w;
            a2.x += w2 * xv.x; a2.y += w2 * xv.y; a2.z += w2 * xv.z; a2.w += w2 * xv.w;
            a3.x += w3 * xv.x; a3.y += w3 * xv.y; a3.z += w3 * xv.z; a3.w += w3 * xv.w;
        }
    }
    size_t base = ((size_t)(b * EE) + te * 4) * DD + d0 + td * 4;
    *reinterpret_cast<float4*>(&g_slots_part[ns][base + 0 * DD]) = a0;
    *reinterpret_cast<float4*>(&g_slots_part[ns][base + 1 * DD]) = a1;
    *reinterpret_cast<float4*>(&g_slots_part[ns][base + 2 * DD]) = a2;
    *reinterpret_cast<float4*>(&g_slots_part[ns][base + 3 * DD]) = a3;

    // ---- last-block reduction for this (b, dt) slice ----
    __threadfence();
    __syncthreads();
    if (t == 0) sred = (atomicAdd(&g_cnt[b * 8 + dt], 1) == 15);
    __syncthreads();
    if (sred) {
        if (t == 0) g_cnt[b * 8 + dt] = 0;   // self-reset
        for (int i = t; i < 1024; i += 256) {
            int e = i >> 5, q = i & 31;
            size_t f4 = ((size_t)(b * EE) + e) * (DD / 4) + dt * 32 + q;
            float4 v = reinterpret_cast<const float4*>(g_slots_part[0])[f4];
#pragma unroll
            for (int p = 1; p < 16; p++) {
                float4 u = reinterpret_cast<const float4*>(g_slots_part[p])[f4];
                v.x += u.x; v.y += u.y; v.z += u.z; v.w += u.w;
            }
            reinterpret_cast<float4*>(g_slots)[f4] = v;
        }
    }
}

// ---------------- K3: w1 pass (k-split 8, 4-deep explicit prefetch) ----------------
// grid (jc=8, ks=8, e=32) = 2048 blocks, 128 threads
__global__ __launch_bounds__(128) void k_w1(const float* __restrict__ w1) {
    int e = blockIdx.z;
    int ks = blockIdx.y;
    int j0 = blockIdx.x * 512 + threadIdx.x * 4;
    int d0 = ks * 128;

    __shared__ float ssp[128 * 4];  // [d][b]
    {
        int d = threadIdx.x;
#pragma unroll
        for (int bb = 0; bb < 4; bb++)
            ssp[d * 4 + bb] = g_slots[(size_t)((bb * EE) + e) * DD + d0 + d];
    }
    __syncthreads();

    const float4* ss4 = reinterpret_cast<const float4*>(ssp);
    float4 a0 = make_float4(0.f, 0.f, 0.f, 0.f), a1 = a0, a2 = a0, a3 = a0;
    const float4* wp = reinterpret_cast<const float4*>(w1 + (size_t)e * DD * HH +
                                                      (size_t)d0 * HH) + (j0 >> 2);

    float4 p0 = __ldcs(wp); wp += (HH / 4);
    float4 p1 = __ldcs(wp); wp += (HH / 4);
    float4 p2 = __ldcs(wp); wp += (HH / 4);
    float4 p3 = __ldcs(wp); wp += (HH / 4);

    for (int d = 0; d < 128; d += 4) {
        float4 c0 = p0, c1 = p1, c2 = p2, c3 = p3;
        if (d < 124) {
            p0 = __ldcs(wp); wp += (HH / 4);
            p1 = __ldcs(wp); wp += (HH / 4);
            p2 = __ldcs(wp); wp += (HH / 4);
            p3 = __ldcs(wp); wp += (HH / 4);
        }
        float4 s0 = ss4[d], s1 = ss4[d + 1], s2 = ss4[d + 2], s3 = ss4[d + 3];
        a0.x += s0.x * c0.x; a0.y += s0.x * c0.y; a0.z += s0.x * c0.z; a0.w += s0.x * c0.w;
        a1.x += s0.y * c0.x; a1.y += s0.y * c0.y; a1.z += s0.y * c0.z; a1.w += s0.y * c0.w;
        a2.x += s0.z * c0.x; a2.y += s0.z * c0.y; a2.z += s0.z * c0.z; a2.w += s0.z * c0.w;
        a3.x += s0.w * c0.x; a3.y += s0.w * c0.y; a3.z += s0.w * c0.z; a3.w += s0.w * c0.w;

        a0.x += s1.x * c1.x; a0.y += s1.x * c1.y; a0.z += s1.x * c1.z; a0.w += s1.x * c1.w;
        a1.x += s1.y * c1.x; a1.y += s1.y * c1.y; a1.z += s1.y * c1.z; a1.w += s1.y * c1.w;
        a2.x += s1.z * c1.x; a2.y += s1.z * c1.y; a2.z += s1.z * c1.z; a2.w += s1.z * c1.w;
        a3.x += s1.w * c1.x; a3.y += s1.w * c1.y; a3.z += s1.w * c1.z; a3.w += s1.w * c1.w;

        a0.x += s2.x * c2.x; a0.y += s2.x * c2.y; a0.z += s2.x * c2.z; a0.w += s2.x * c2.w;
        a1.x += s2.y * c2.x; a1.y += s2.y * c2.y; a1.z += s2.y * c2.z; a1.w += s2.y * c2.w;
        a2.x += s2.z * c2.x; a2.y += s2.z * c2.y; a2.z += s2.z * c2.z; a2.w += s2.z * c2.w;
        a3.x += s2.w * c2.x; a3.y += s2.w * c2.y; a3.z += s2.w * c2.z; a3.w += s2.w * c2.w;

        a0.x += s3.x * c3.x; a0.y += s3.x * c3.y; a0.z += s3.x * c3.z; a0.w += s3.x * c3.w;
        a1.x += s3.y * c3.x; a1.y += s3.y * c3.y; a1.z += s3.y * c3.z; a1.w += s3.y * c3.w;
        a2.x += s3.z * c3.x; a2.y += s3.z * c3.y; a2.z += s3.z * c3.z; a2.w += s3.z * c3.w;
        a3.x += s3.w * c3.x; a3.y += s3.w * c3.y; a3.z += s3.w * c3.z; a3.w += s3.w * c3.w;
    }
    *reinterpret_cast<float4*>(&g_h1p[ks][(size_t)(e * 4 + 0) * HH + j0]) = a0;
    *reinterpret_cast<float4*>(&g_h1p[ks][(size_t)(e * 4 + 1) * HH + j0]) = a1;
    *reinterpret_cast<float4*>(&g_h1p[ks][(size_t)(e * 4 + 2) * HH + j0]) = a2;
    *reinterpret_cast<float4*>(&g_h1p[ks][(size_t)(e * 4 + 3) * HH + j0]) = a3;
}

// ---------------- K4: w2 pass (8-deep explicit prefetch) + fused eo reduce ----------------
// grid (hs=32, e=32) = 1024 blocks, 256 threads
__global__ __launch_bounds__(256) void k_w2(
    const float* __restrict__ w2, const float* __restrict__ b1,
    const float* __restrict__ b2) {
    int e = blockIdx.y;
    int hs = blockIdx.x;
    int h0 = hs * 128;
    int t = threadIdx.x;

    __shared__ float4 hsm4[128];  // [hh] -> (b0,b1,b2,b3)
    __shared__ bool sred;
    for (int i = t; i < 512; i += 256) {
        int b = i >> 7, hh = i & 127;
        size_t hidx = (size_t)(e * 4 + b) * HH + h0 + hh;
        float v = b1[e * HH + h0 + hh];
#pragma unroll
        for (int p = 0; p < 8; p++) v += g_h1p[p][hidx];
        v = v * normcdff(v);
        reinterpret_cast<float*>(hsm4)[hh * 4 + b] = v;
    }
    __syncthreads();

    float4 a0 = make_float4(0.f, 0.f, 0.f, 0.f), a1 = a0, a2 = a0, a3 = a0;
    const float4* wp = reinterpret_cast<const float4*>(
        w2 + (size_t)e * HH * DD + (size_t)h0 * DD) + t;

    // 8-deep prefetch pipeline
    float4 p0 = __ldcs(wp); wp += (DD / 4);
    float4 p1 = __ldcs(wp); wp += (DD / 4);
    float4 p2 = __ldcs(wp); wp += (DD / 4);
    float4 p3 = __ldcs(wp); wp += (DD / 4);
    float4 p4 = __ldcs(wp); wp += (DD / 4);
    float4 p5 = __ldcs(wp); wp += (DD / 4);
    float4 p6 = __ldcs(wp); wp += (DD / 4);
    float4 p7 = __ldcs(wp); wp += (DD / 4);

    for (int hh = 0; hh < 128; hh += 8) {
        float4 c0 = p0, c1 = p1, c2 = p2, c3 = p3, c4 = p4, c5 = p5, c6 = p6, c7 = p7;
        if (hh < 120) {
            p0 = __ldcs(wp); wp += (DD / 4);
            p1 = __ldcs(wp); wp += (DD / 4);
            p2 = __ldcs(wp); wp += (DD / 4);
            p3 = __ldcs(wp); wp += (DD / 4);
            p4 = __ldcs(wp); wp += (DD / 4);
            p5 = __ldcs(wp); wp += (DD / 4);
            p6 = __ldcs(wp); wp += (DD / 4);
            p7 = __ldcs(wp); wp += (DD / 4);
        }
#pragma unroll
        for (int u = 0; u < 8; u++) {
            float4 cv = (u == 0) ? c0 : (u == 1) ? c1 : (u == 2) ? c2 : (u == 3) ? c3 :
                        (u == 4) ? c4 : (u == 5) ? c5 : (u == 6) ? c6 : c7;
            float4 hv = hsm4[hh + u];
            a0.x += hv.x * cv.x; a0.y += hv.x * cv.y; a0.z += hv.x * cv.z; a0.w += hv.x * cv.w;
            a1.x += hv.y * cv.x; a1.y += hv.y * cv.y; a1.z += hv.y * cv.z; a1.w += hv.y * cv.w;
            a2.x += hv.z * cv.x; a2.y += hv.z * cv.y; a2.z += hv.z * cv.z; a2.w += hv.z * cv.w;
            a3.x += hv.w * cv.x; a3.y += hv.w * cv.y; a3.z += hv.w * cv.z; a3.w += hv.w * cv.w;
        }
    }

    int d0 = t * 4;
    *reinterpret_cast<float4*>(&g_eo_part[hs][((0 * EE) + e) * DD + d0]) = a0;
    *reinterpret_cast<float4*>(&g_eo_part[hs][((1 * EE) + e) * DD + d0]) = a1;
    *reinterpret_cast<float4*>(&g_eo_part[hs][((2 * EE) + e) * DD + d0]) = a2;
    *reinterpret_cast<float4*>(&g_eo_part[hs][((3 * EE) + e) * DD + d0]) = a3;

    // ---- last-block eo reduction for this e (32 hs arrivals) ----
    __threadfence();
    __syncthreads();
    if (t == 0) sred = (atomicAdd(&g_cnt[64 + e], 1) == 31);
    __syncthreads();
    if (sred) {
        if (t == 0) g_cnt[64 + e] = 0;   // self-reset
        for (int i = t; i < 1024; i += 256) {
            int b = i >> 8;            // 0..3
            int q = i & 255;           // float4 within DD
            size_t f4 = ((size_t)(b * EE) + e) * (DD / 4) + q;
            float4 s = reinterpret_cast<const float4*>(b2)[e * (DD / 4) + q];
#pragma unroll
            for (int p = 0; p < 32; p++) {
                float4 u = reinterpret_cast<const float4*>(g_eo_part[p])[f4];
                s.x += u.x; s.y += u.y; s.z += u.z; s.w += u.w;
            }
            reinterpret_cast<float4*>(g_eo)[f4] = s;
        }
    }
}

// ---------------- K5: out (register micro-tile GEMM over e) ----------------
// grid (dt=8, nt=32, b=4) = 1024 blocks; thread: 4n x 4d (float4)
__global__ __launch_bounds__(256) void k_out(float* __restrict__ out) {
    int dt = blockIdx.x;
    int nt = blockIdx.y;
    int b = blockIdx.z;
    int t = threadIdx.x;
    int td = t & 31;
    int tn = t >> 5;   // 0..7 -> rows tn*4..tn*4+3
    int d0 = dt * 128;
    int n0 = nt * 32;

    __shared__ float4 eos4[32][32];  // [e][d-quad], 16 KB
    __shared__ float cwTs[32][33];   // [e][nn]

    for (int i = t; i < 1024; i += 256) {
        int e = i >> 5, q = i & 31;
        eos4[e][q] = *reinterpret_cast<const float4*>(
            &g_eo[((b * EE) + e) * DD + d0 + q * 4]);
    }
    {
        int nn = t >> 3, equad = t & 7;
        float4 v = *reinterpret_cast<const float4*>(
            &g_cw[((size_t)(b * NN) + n0 + nn) * EE + equad * 4]);
        cwTs[equad * 4 + 0][nn] = v.x;
        cwTs[equad * 4 + 1][nn] = v.y;
        cwTs[equad * 4 + 2][nn] = v.z;
        cwTs[equad * 4 + 3][nn] = v.w;
    }
    __syncthreads();

    float4 a0 = make_float4(0.f, 0.f, 0.f, 0.f), a1 = a0, a2 = a0, a3 = a0;
#pragma unroll
    for (int e = 0; e < 32; e++) {
        float4 ev = eos4[e][td];
        float c0 = cwTs[e][tn * 4 + 0];
        float c1 = cwTs[e][tn * 4 + 1];
        float c2 = cwTs[e][tn * 4 + 2];
        float c3 = cwTs[e][tn * 4 + 3];
        a0.x += c0 * ev.x; a0.y += c0 * ev.y; a0.z += c0 * ev.z; a0.w += c0 * ev.w;
        a1.x += c1 * ev.x; a1.y += c1 * ev.y; a1.z += c1 * ev.z; a1.w += c1 * ev.w;
        a2.x += c2 * ev.x; a2.y += c2 * ev.y; a2.z += c2 * ev.z; a2.w += c2 * ev.w;
        a3.x += c3 * ev.x; a3.y += c3 * ev.y; a3.z += c3 * ev.z; a3.w += c3 * ev.w;
    }
    size_t base = ((size_t)(b * NN) + n0 + tn * 4) * DD + d0 + td * 4;
    *reinterpret_cast<float4*>(&out[base + 0 * DD]) = a0;
    *reinterpret_cast<float4*>(&out[base + 1 * DD]) = a1;
    *reinterpret_cast<float4*>(&out[base + 2 * DD]) = a2;
    *reinterpret_cast<float4*>(&out[base + 3 * DD]) = a3;
}

// ---------------- launch ----------------
extern "C" void kernel_launch(void* const* d_in, const int* in_sizes, int n_in,
                              void* d_out, int out_size) {
    const float* x   = (const float*)d_in[0];
    const float* phi = (const float*)d_in[1];
    const float* kg  = (const float*)d_in[2];
    const float* kb  = (const float*)d_in[3];
    const float* qg  = (const float*)d_in[4];
    const float* qb  = (const float*)d_in[5];
    const float* lg  = (const float*)d_in[6];
    const float* lb  = (const float*)d_in[7];
    const float* sc  = (const float*)d_in[8];
    const float* w1  = (const float*)d_in[9];
    const float* b1  = (const float*)d_in[10];
    const float* w2  = (const float*)d_in[11];
    const float* b2  = (const float*)d_in[12];
    float* out = (float*)d_out;

    k_logits<<<dim3(32, 4), 256>>>(x, kg, kb, phi, qg, qb, lg, lb, sc, out);  // 1 (+qnorm +combine +dstats +scalars)
    k_slots<<<dim3(8, 16, 4), 256>>>(x);                                      // 2 (+reduce)
    k_w1<<<dim3(8, 8, 32), 128>>>(w1);                                        // 3 (prefetch)
    k_w2<<<dim3(32, 32), 256>>>(w2, b1, b2);                                  // 4 <- ncu capture (8-deep prefetch +eo reduce)
    k_out<<<dim3(8, 32, 4), 256>>>(out);                                      // 5
}

// round 13
// speedup vs baseline: 1.0667x; 1.0667x over previous
#include <cuda_runtime.h>
#include <math.h>
#include <stddef.h>

#define BB 4
#define NN 1024
#define DD 1024
#define EE 32
#define HH 4096
#define LN_EPS 1e-5f
#define PS_EPS 1e-9f

// ---------------- scratch (device globals) ----------------
__device__ __align__(16) float g_logits[BB * NN * EE];    // [b][n][e]
__device__ __align__(16) float g_logitsT[BB * EE * NN];   // [b][e][n]
__device__ __align__(16) float g_cw[BB * NN * EE];        // combine weights [b][n][e]
__device__ __align__(16) float2 g_minv[BB * EE];          // (max, 1/sum) per (b,e)
__device__ float g_cwterm[BB * NN];
__device__ float g_cwdiag[BB * EE];
__device__ float g_dwterm[BB * EE];
__device__ __align__(16) float g_slots_part[16][BB * EE * DD];
__device__ __align__(16) float g_slots[BB * EE * DD];
__device__ int g_cnt[64];   // [32..35] logits-batch, [48] combine (self-resetting)
__device__ __align__(16) float g_h1p[8][EE * BB * HH];    // pre-gelu partials (k-split 8)
__device__ __align__(16) float g_eo_part[32][BB * EE * DD];
__device__ __align__(16) float g_eo[BB * EE * DD];

__device__ __forceinline__ float fold_dq(float v) {
    v += __shfl_xor_sync(0xffffffffu, v, 8);
    v += __shfl_xor_sync(0xffffffffu, v, 16);
    return v;
}

// ---------------- K1: logits (qnorm fused; dstats fused via last-block-per-batch) ----------------
// grid (nt=32, b=4) = 128 blocks, 256 threads.
__global__ __launch_bounds__(256) void k_logits(
    const float* __restrict__ x, const float* __restrict__ kg,
    const float* __restrict__ kb,
    const float* __restrict__ phi, const float* __restrict__ qg,
    const float* __restrict__ qb, const float* __restrict__ lng,
    const float* __restrict__ lnb, const float* __restrict__ scale_p) {
    int b = blockIdx.y;
    int n0 = blockIdx.x * 32;
    int t = threadIdx.x;
    int eq = t >> 5;         // 0..7
    int dq = (t >> 3) & 3;   // 0..3
    int nq = t & 7;          // 0..7

    __shared__ float xsT[128][36];  // [d within chunk][n]
    __shared__ float qsT[128][36];  // [d within chunk][e]
    __shared__ float sm_mean[EE], sm_rstd[EE];
    __shared__ bool sdo;

    int w = t >> 5, l = t & 31;

    // ---- Phase A: per-expert LN stats (one-pass) ----
#pragma unroll
    for (int ei = 0; ei < 4; ei++) {
        int e = w + ei * 8;
        float s1 = 0.f, s2 = 0.f;
#pragma unroll 4
        for (int k = 0; k < 32; k++) {
            int d = l + 32 * k;
            float v = phi[e * DD + d] * qg[d] + qb[d];
            s1 += v; s2 += v * v;
        }
#pragma unroll
        for (int o = 16; o; o >>= 1) {
            s1 += __shfl_xor_sync(0xffffffffu, s1, o);
            s2 += __shfl_xor_sync(0xffffffffu, s2, o);
        }
        if (l == 0) {
            float mean = s1 * (1.f / DD);
            float var = s2 * (1.f / DD) - mean * mean;
            sm_mean[e] = mean;
            sm_rstd[e] = rsqrtf(var + LN_EPS);
        }
    }
    float sc = *scale_p;

    int dseg = (w & 3) * 32;        // d-segment within 128-chunk
    int half = (w >> 2) * 16;       // n-half / e-half

    float4 aN0 = make_float4(0.f, 0.f, 0.f, 0.f), aN1 = aN0, aN2 = aN0, aN3 = aN0;

    for (int c = 0; c < 8; c++) {
        int dd0 = dseg + l;              // 0..127
        int dglob = c * 128 + dd0;
        float kgv = kg[dglob], kbv = kb[dglob];
        float qgv = qg[dglob], qbv = qb[dglob];
        float lngv = lng[dglob], lnbv = lnb[dglob];
        __syncthreads();
#pragma unroll
        for (int i = 0; i < 16; i++) {
            int n = half + i;
            xsT[dd0][n] = x[((size_t)(b * NN) + n0 + n) * DD + dglob] * kgv + kbv;
            float v = phi[n * DD + dglob] * qgv + qbv;   // n doubles as expert row
            qsT[dd0][n] = ((v - sm_mean[n]) * sm_rstd[n] * lngv + lnbv) * sc;
        }
        __syncthreads();
#pragma unroll
        for (int k = 0; k < 32; k++) {
            int dd = dq * 32 + k;
            float4 xv = *reinterpret_cast<const float4*>(&xsT[dd][nq * 4]);
            float4 qv = *reinterpret_cast<const float4*>(&qsT[dd][eq * 4]);
            aN0.x += xv.x * qv.x; aN0.y += xv.x * qv.y; aN0.z += xv.x * qv.z; aN0.w += xv.x * qv.w;
            aN1.x += xv.y * qv.x; aN1.y += xv.y * qv.y; aN1.z += xv.y * qv.z; aN1.w += xv.y * qv.w;
            aN2.x += xv.z * qv.x; aN2.y += xv.z * qv.y; aN2.z += xv.z * qv.z; aN2.w += xv.z * qv.w;
            aN3.x += xv.w * qv.x; aN3.y += xv.w * qv.y; aN3.z += xv.w * qv.z; aN3.w += xv.w * qv.w;
        }
    }

    aN0.x = fold_dq(aN0.x); aN0.y = fold_dq(aN0.y); aN0.z = fold_dq(aN0.z); aN0.w = fold_dq(aN0.w);
    aN1.x = fold_dq(aN1.x); aN1.y = fold_dq(aN1.y); aN1.z = fold_dq(aN1.z); aN1.w = fold_dq(aN1.w);
    aN2.x = fold_dq(aN2.x); aN2.y = fold_dq(aN2.y); aN2.z = fold_dq(aN2.z); aN2.w = fold_dq(aN2.w);
    aN3.x = fold_dq(aN3.x); aN3.y = fold_dq(aN3.y); aN3.z = fold_dq(aN3.z); aN3.w = fold_dq(aN3.w);

    if (dq == 0) {
        float4 accs[4] = {aN0, aN1, aN2, aN3};
#pragma unroll
        for (int i = 0; i < 4; i++) {
            int n = n0 + nq * 4 + i;
            *reinterpret_cast<float4*>(&g_logits[((b * NN) + n) * EE + eq * 4]) = accs[i];
            g_logitsT[((size_t)(b * EE) + eq * 4 + 0) * NN + n] = accs[i].x;
            g_logitsT[((size_t)(b * EE) + eq * 4 + 1) * NN + n] = accs[i].y;
            g_logitsT[((size_t)(b * EE) + eq * 4 + 2) * NN + n] = accs[i].z;
            g_logitsT[((size_t)(b * EE) + eq * 4 + 3) * NN + n] = accs[i].w;
        }
    }

    // ---- last-block dstats for this batch (reads only 128 KB; cheap tail) ----
    __threadfence();
    __syncthreads();
    if (t == 0) sdo = (atomicAdd(&g_cnt[32 + b], 1) == 31);
    __syncthreads();
    if (sdo) {
        if (t == 0) g_cnt[32 + b] = 0;   // self-reset
#pragma unroll
        for (int ei = 0; ei < 4; ei++) {
            int e = w * 4 + ei;
            const float* L = g_logitsT + ((size_t)(b * EE) + e) * NN;
            float m = -1e30f;
#pragma unroll 4
            for (int k = 0; k < 32; k++) m = fmaxf(m, L[k * 32 + l]);
#pragma unroll
            for (int o = 16; o; o >>= 1) m = fmaxf(m, __shfl_xor_sync(0xffffffffu, m, o));
            float s1 = 0.f, s2 = 0.f;
#pragma unroll 4
            for (int k = 0; k < 32; k++) {
                float ex = expf(L[k * 32 + l] - m);
                s1 += ex; s2 += ex * ex;
            }
#pragma unroll
            for (int o = 16; o; o >>= 1) {
                s1 += __shfl_xor_sync(0xffffffffu, s1, o);
                s2 += __shfl_xor_sync(0xffffffffu, s2, o);
            }
            if (l == 0) {
                float inv = 1.f / s1;
                g_minv[b * EE + e] = make_float2(m, inv);
                float wsq = s2 * inv * inv;
                float rs = rsqrtf(wsq + PS_EPS);
                float rn = (s1 * inv) * rs;
                g_dwterm[b * EE + e] = rn * rn;
            }
        }
    }
}

// ---------------- K2: slots partials (no tail) ----------------
// grid (dt=8, ns=16, b=4) = 512 blocks; thread: 4e x 4d (float4), 16 accs
__global__ __launch_bounds__(256) void k_slots(const float* __restrict__ x) {
    int dt = blockIdx.x;
    int ns = blockIdx.y;
    int b = blockIdx.z;
    int t = threadIdx.x;
    int td = t & 31;   // d-quad
    int te = t >> 5;   // 0..7 -> experts te*4..te*4+3
    int d0 = dt * 128;
    int n0 = ns * 64;

    __shared__ float4 xs4[32][32];   // [nn][d-quad], 16 KB
    __shared__ float dwsT[32][33];   // [e][nn]

    float4 a0 = make_float4(0.f, 0.f, 0.f, 0.f), a1 = a0, a2 = a0, a3 = a0;

    for (int c = 0; c < 2; c++) {
        int nc = n0 + c * 32;
        __syncthreads();
        for (int i = t; i < 1024; i += 256) {
            int row = i >> 5, q = i & 31;
            xs4[row][q] = *reinterpret_cast<const float4*>(
                x + ((size_t)(b * NN) + nc + row) * DD + d0 + q * 4);
        }
        for (int i = t; i < 1024; i += 256) {
            int e = i >> 5, nn = i & 31;
            float2 mi = g_minv[b * EE + e];
            float lv = g_logitsT[((size_t)(b * EE) + e) * NN + nc + nn];
            dwsT[e][nn] = expf(lv - mi.x) * mi.y;
        }
        __syncthreads();
#pragma unroll
        for (int k = 0; k < 32; k++) {
            float4 xv = xs4[k][td];
            float w0 = dwsT[te * 4 + 0][k];
            float w1 = dwsT[te * 4 + 1][k];
            float w2 = dwsT[te * 4 + 2][k];
            float w3 = dwsT[te * 4 + 3][k];
            a0.x += w0 * xv.x; a0.y += w0 * xv.y; a0.z += w0 * xv.z; a0.w += w0 * xv.w;
            a1.x += w1 * xv.x; a1.y += w1 * xv.y; a1.z += w1 * xv.z; a1.w += w1 * xv.w;
            a2.x += w2 * xv.x; a2.y += w2 * xv.y; a2.z += w2 * xv.z; a2.w += w2 * xv.w;
            a3.x += w3 * xv.x; a3.y += w3 * xv.y; a3.z += w3 * xv.z; a3.w += w3 * xv.w;
        }
    }
    size_t base = ((size_t)(b * EE) + te * 4) * DD + d0 + td * 4;
    *reinterpret_cast<float4*>(&g_slots_part[ns][base + 0 * DD]) = a0;
    *reinterpret_cast<float4*>(&g_slots_part[ns][base + 1 * DD]) = a1;
    *reinterpret_cast<float4*>(&g_slots_part[ns][base + 2 * DD]) = a2;
    *reinterpret_cast<float4*>(&g_slots_part[ns][base + 3 * DD]) = a3;
}

// ---------------- K2b: dedicated slot-partial reduce (full-chip parallelism) ----------------
__global__ __launch_bounds__(256) void k_red_slots() {
    int i = blockIdx.x * 256 + threadIdx.x;  // 32768 float4s
    float4 v = reinterpret_cast<const float4*>(g_slots_part[0])[i];
#pragma unroll
    for (int p = 1; p < 16; p++) {
        float4 u = reinterpret_cast<const float4*>(g_slots_part[p])[i];
        v.x += u.x; v.y += u.y; v.z += u.z; v.w += u.w;
    }
    reinterpret_cast<float4*>(g_slots)[i] = v;
}

// ---------------- K3: w1 pass (k-split 8; proven 84us @ 82% DRAM config) ----------------
// grid (jc=8, ks=8, e=32) = 2048 blocks, 128 threads
__global__ __launch_bounds__(128) void k_w1(const float* __restrict__ w1) {
    int e = blockIdx.z;
    int ks = blockIdx.y;
    int j0 = blockIdx.x * 512 + threadIdx.x * 4;
    int d0 = ks * 128;

    __shared__ float ssp[128 * 4];  // [d][b]
    {
        int d = threadIdx.x;
#pragma unroll
        for (int bb = 0; bb < 4; bb++)
            ssp[d * 4 + bb] = g_slots[(size_t)((bb * EE) + e) * DD + d0 + d];
    }
    __syncthreads();

    const float4* ss4 = reinterpret_cast<const float4*>(ssp);
    float4 a0 = make_float4(0.f, 0.f, 0.f, 0.f), a1 = a0, a2 = a0, a3 = a0;
    const float4* wp = reinterpret_cast<const float4*>(w1 + (size_t)e * DD * HH +
                                                      (size_t)d0 * HH) + (j0 >> 2);
#pragma unroll 8
    for (int d = 0; d < 128; d++) {
        float4 wv = __ldcs(wp);
        wp += (HH / 4);
        float4 sv = ss4[d];
        a0.x += sv.x * wv.x; a0.y += sv.x * wv.y; a0.z += sv.x * wv.z; a0.w += sv.x * wv.w;
        a1.x += sv.y * wv.x; a1.y += sv.y * wv.y; a1.z += sv.y * wv.z; a1.w += sv.y * wv.w;
        a2.x += sv.z * wv.x; a2.y += sv.z * wv.y; a2.z += sv.z * wv.z; a2.w += sv.z * wv.w;
        a3.x += sv.w * wv.x; a3.y += sv.w * wv.y; a3.z += sv.w * wv.z; a3.w += sv.w * wv.w;
    }
    *reinterpret_cast<float4*>(&g_h1p[ks][(size_t)(e * 4 + 0) * HH + j0]) = a0;
    *reinterpret_cast<float4*>(&g_h1p[ks][(size_t)(e * 4 + 1) * HH + j0]) = a1;
    *reinterpret_cast<float4*>(&g_h1p[ks][(size_t)(e * 4 + 2) * HH + j0]) = a2;
    *reinterpret_cast<float4*>(&g_h1p[ks][(size_t)(e * 4 + 3) * HH + j0]) = a3;
}

// ---------------- K4: w2 pass (4-deep prefetch; proven 93.8us config, tail removed) ----------------
// grid (hs=32, e=32) = 1024 blocks, 256 threads
__global__ __launch_bounds__(256) void k_w2(
    const float* __restrict__ w2, const float* __restrict__ b1) {
    int e = blockIdx.y;
    int hs = blockIdx.x;
    int h0 = hs * 128;
    int t = threadIdx.x;

    __shared__ float4 hsm4[128];  // [hh] -> (b0,b1,b2,b3)
    for (int i = t; i < 512; i += 256) {
        int b = i >> 7, hh = i & 127;
        size_t hidx = (size_t)(e * 4 + b) * HH + h0 + hh;
        float v = b1[e * HH + h0 + hh];
#pragma unroll
        for (int p = 0; p < 8; p++) v += g_h1p[p][hidx];
        v = v * normcdff(v);
        reinterpret_cast<float*>(hsm4)[hh * 4 + b] = v;
    }
    __syncthreads();

    float4 a0 = make_float4(0.f, 0.f, 0.f, 0.f), a1 = a0, a2 = a0, a3 = a0;
    const float4* wp = reinterpret_cast<const float4*>(
        w2 + (size_t)e * HH * DD + (size_t)h0 * DD) + t;

    // 4-deep prefetch pipeline (validated knee)
    float4 p0 = __ldcs(wp); wp += (DD / 4);
    float4 p1 = __ldcs(wp); wp += (DD / 4);
    float4 p2 = __ldcs(wp); wp += (DD / 4);
    float4 p3 = __ldcs(wp); wp += (DD / 4);

    for (int hh = 0; hh < 128; hh += 4) {
        float4 c0 = p0, c1 = p1, c2 = p2, c3 = p3;
        if (hh < 124) {
            p0 = __ldcs(wp); wp += (DD / 4);
            p1 = __ldcs(wp); wp += (DD / 4);
            p2 = __ldcs(wp); wp += (DD / 4);
            p3 = __ldcs(wp); wp += (DD / 4);
        }
        float4 h0v = hsm4[hh], h1v = hsm4[hh + 1], h2v = hsm4[hh + 2], h3v = hsm4[hh + 3];
        a0.x += h0v.x * c0.x; a0.y += h0v.x * c0.y; a0.z += h0v.x * c0.z; a0.w += h0v.x * c0.w;
        a1.x += h0v.y * c0.x; a1.y += h0v.y * c0.y; a1.z += h0v.y * c0.z; a1.w += h0v.y * c0.w;
        a2.x += h0v.z * c0.x; a2.y += h0v.z * c0.y; a2.z += h0v.z * c0.z; a2.w += h0v.z * c0.w;
        a3.x += h0v.w * c0.x; a3.y += h0v.w * c0.y; a3.z += h0v.w * c0.z; a3.w += h0v.w * c0.w;

        a0.x += h1v.x * c1.x; a0.y += h1v.x * c1.y; a0.z += h1v.x * c1.z; a0.w += h1v.x * c1.w;
        a1.x += h1v.y * c1.x; a1.y += h1v.y * c1.y; a1.z += h1v.y * c1.z; a1.w += h1v.y * c1.w;
        a2.x += h1v.z * c1.x; a2.y += h1v.z * c1.y; a2.z += h1v.z * c1.z; a2.w += h1v.z * c1.w;
        a3.x += h1v.w * c1.x; a3.y += h1v.w * c1.y; a3.z += h1v.w * c1.z; a3.w += h1v.w * c1.w;

        a0.x += h2v.x * c2.x; a0.y += h2v.x * c2.y; a0.z += h2v.x * c2.z; a0.w += h2v.x * c2.w;
        a1.x += h2v.y * c2.x; a1.y += h2v.y * c2.y; a1.z += h2v.y * c2.z; a1.w += h2v.y * c2.w;
        a2.x += h2v.z * c2.x; a2.y += h2v.z * c2.y; a2.z += h2v.z * c2.z; a2.w += h2v.z * c2.w;
        a3.x += h2v.w * c2.x; a3.y += h2v.w * c2.y; a3.z += h2v.w * c2.z; a3.w += h2v.w * c2.w;

        a0.x += h3v.x * c3.x; a0.y += h3v.x * c3.y; a0.z += h3v.x * c3.z; a0.w += h3v.x * c3.w;
        a1.x += h3v.y * c3.x; a1.y += h3v.y * c3.y; a1.z += h3v.y * c3.z; a1.w += h3v.y * c3.w;
        a2.x += h3v.z * c3.x; a2.y += h3v.z * c3.y; a2.z += h3v.z * c3.z; a2.w += h3v.z * c3.w;
        a3.x += h3v.w * c3.x; a3.y += h3v.w * c3.y; a3.z += h3v.w * c3.z; a3.w += h3v.w * c3.w;
    }

    int d0 = t * 4;
    *reinterpret_cast<float4*>(&g_eo_part[hs][((0 * EE) + e) * DD + d0]) = a0;
    *reinterpret_cast<float4*>(&g_eo_part[hs][((1 * EE) + e) * DD + d0]) = a1;
    *reinterpret_cast<float4*>(&g_eo_part[hs][((2 * EE) + e) * DD + d0]) = a2;
    *reinterpret_cast<float4*>(&g_eo_part[hs][((3 * EE) + e) * DD + d0]) = a3;
}

// ---------------- K4b: dedicated eo-partial reduce (+b2), full-chip parallelism ----------------
__global__ __launch_bounds__(256) void k_red_eo(const float* __restrict__ b2) {
    int i = blockIdx.x * 256 + threadIdx.x;  // 32768 float4s
    int e = (i >> 8) & (EE - 1);
    int dqd = i & 255;
    float4 s = reinterpret_cast<const float4*>(b2)[e * 256 + dqd];
#pragma unroll
    for (int p = 0; p < 32; p++) {
        float4 u = reinterpret_cast<const float4*>(g_eo_part[p])[i];
        s.x += u.x; s.y += u.y; s.z += u.z; s.w += u.w;
    }
    reinterpret_cast<float4*>(g_eo)[i] = s;
}

// ---------------- K5: combine softmax + cw metric terms + fused scalars ----------------
__global__ __launch_bounds__(256) void k_combine(float* __restrict__ out) {
    int t = threadIdx.x;
    int w = t >> 5, l = t & 31;
    int bn0 = blockIdx.x * 64;
    __shared__ float cs[64][33];
    __shared__ bool sdo;

#pragma unroll
    for (int k = 0; k < 2; k++) {
        int f = t + k * 256;
        int row = f >> 3, q = f & 7;
        float4 v = *reinterpret_cast<const float4*>(&g_logits[(bn0 + row) * EE + q * 4]);
        cs[row][q * 4 + 0] = v.x; cs[row][q * 4 + 1] = v.y;
        cs[row][q * 4 + 2] = v.z; cs[row][q * 4 + 3] = v.w;
    }
    __syncthreads();

    int r = w * 8 + (l >> 2);
    int j = l & 3;
    float v[8];
#pragma unroll
    for (int i = 0; i < 8; i++) v[i] = cs[r][j * 8 + i];

    float m = v[0];
#pragma unroll
    for (int i = 1; i < 8; i++) m = fmaxf(m, v[i]);
    m = fmaxf(m, __shfl_xor_sync(0xffffffffu, m, 1));
    m = fmaxf(m, __shfl_xor_sync(0xffffffffu, m, 2));

    float ex[8], s = 0.f;
#pragma unroll
    for (int i = 0; i < 8; i++) { ex[i] = expf(v[i] - m); s += ex[i]; }
    s += __shfl_xor_sync(0xffffffffu, s, 1);
    s += __shfl_xor_sync(0xffffffffu, s, 2);
    float inv = 1.f / s;

    float cw[8], sq = 0.f, sc = 0.f;
#pragma unroll
    for (int i = 0; i < 8; i++) { cw[i] = ex[i] * inv; sq += cw[i] * cw[i]; sc += cw[i]; }
    sq += __shfl_xor_sync(0xffffffffu, sq, 1);
    sq += __shfl_xor_sync(0xffffffffu, sq, 2);
    sc += __shfl_xor_sync(0xffffffffu, sc, 1);
    sc += __shfl_xor_sync(0xffffffffu, sc, 2);

    int bn = bn0 + r;
    *reinterpret_cast<float4*>(&g_cw[bn * EE + j * 8]) =
        make_float4(cw[0], cw[1], cw[2], cw[3]);
    *reinterpret_cast<float4*>(&g_cw[bn * EE + j * 8 + 4]) =
        make_float4(cw[4], cw[5], cw[6], cw[7]);

    float rs = rsqrtf(sq + PS_EPS);
    float rows = sc * rs;
    int n = bn & (NN - 1);
    int b = bn >> 10;
    if (j == 0) g_cwterm[bn] = rows * rows;
    if (n < EE && j == (n >> 3))
        g_cwdiag[b * EE + n] = cw[n & 7] * rs * rows;

    // ---- last-block scalar reduction (reads ~20 KB; cheap tail) ----
    __threadfence();
    __syncthreads();
    if (t == 0) sdo = (atomicAdd(&g_cnt[48], 1) == 63);
    __syncthreads();
    if (sdo) {
        __shared__ float red[256];
        if (t == 0) g_cnt[48] = 0;   // self-reset
        float vv;

        vv = 0.f; for (int i = t; i < BB * NN; i += 256) vv += g_cwterm[i];
        red[t] = vv; __syncthreads();
        for (int st = 128; st > 0; st >>= 1) { if (t < st) red[t] += red[t + st]; __syncthreads(); }
        float sumA = red[0]; __syncthreads();

        vv = 0.f; for (int i = t; i < BB * EE; i += 256) vv += g_cwdiag[i];
        red[t] = vv; __syncthreads();
        for (int st = 128; st > 0; st >>= 1) { if (t < st) red[t] += red[t + st]; __syncthreads(); }
        float sumAd = red[0]; __syncthreads();

        vv = 0.f; for (int i = t; i < BB * EE; i += 256) vv += g_dwterm[i];
        red[t] = vv; __syncthreads();
        for (int st = 128; st > 0; st >>= 1) { if (t < st) red[t] += red[t + st]; __syncthreads(); }
        float sumB = red[0]; __syncthreads();

        vv = (t < BB) ? g_dwterm[t * EE] : 0.f;
        red[t] = vv; __syncthreads();
        for (int st = 128; st > 0; st >>= 1) { if (t < st) red[t] += red[t + st]; __syncthreads(); }
        float sumB0 = red[0];

        if (t == 0) {
            out[(size_t)BB * NN * DD]     = (sumA - sumAd) / (float)(BB * (size_t)NN * (NN - 1));
            out[(size_t)BB * NN * DD + 1] = (sumB - sumB0) / (float)(BB * EE * (EE - 1));
        }
    }
}

// ---------------- K6: out (register micro-tile GEMM over e) ----------------
// grid (dt=8, nt=32, b=4) = 1024 blocks; thread: 4n x 4d (float4)
__global__ __launch_bounds__(256) void k_out(float* __restrict__ out) {
    int dt = blockIdx.x;
    int nt = blockIdx.y;
    int b = blockIdx.z;
    int t = threadIdx.x;
    int td = t & 31;
    int tn = t >> 5;   // 0..7 -> rows tn*4..tn*4+3
    int d0 = dt * 128;
    int n0 = nt * 32;

    __shared__ float4 eos4[32][32];  // [e][d-quad], 16 KB
    __shared__ float cwTs[32][33];   // [e][nn]

    for (int i = t; i < 1024; i += 256) {
        int e = i >> 5, q = i & 31;
        eos4[e][q] = *reinterpret_cast<const float4*>(
            &g_eo[((b * EE) + e) * DD + d0 + q * 4]);
    }
    {
        int nn = t >> 3, equad = t & 7;
        float4 v = *reinterpret_cast<const float4*>(
            &g_cw[((size_t)(b * NN) + n0 + nn) * EE + equad * 4]);
        cwTs[equad * 4 + 0][nn] = v.x;
        cwTs[equad * 4 + 1][nn] = v.y;
        cwTs[equad * 4 + 2][nn] = v.z;
        cwTs[equad * 4 + 3][nn] = v.w;
    }
    __syncthreads();

    float4 a0 = make_float4(0.f, 0.f, 0.f, 0.f), a1 = a0, a2 = a0, a3 = a0;
#pragma unroll
    for (int e = 0; e < 32; e++) {
        float4 ev = eos4[e][td];
        float c0 = cwTs[e][tn * 4 + 0];
        float c1 = cwTs[e][tn * 4 + 1];
        float c2 = cwTs[e][tn * 4 + 2];
        float c3 = cwTs[e][tn * 4 + 3];
        a0.x += c0 * ev.x; a0.y += c0 * ev.y; a0.z += c0 * ev.z; a0.w += c0 * ev.w;
        a1.x += c1 * ev.x; a1.y += c1 * ev.y; a1.z += c1 * ev.z; a1.w += c1 * ev.w;
        a2.x += c2 * ev.x; a2.y += c2 * ev.y; a2.z += c2 * ev.z; a2.w += c2 * ev.w;
        a3.x += c3 * ev.x; a3.y += c3 * ev.y; a3.z += c3 * ev.z; a3.w += c3 * ev.w;
    }
    size_t base = ((size_t)(b * NN) + n0 + tn * 4) * DD + d0 + td * 4;
    *reinterpret_cast<float4*>(&out[base + 0 * DD]) = a0;
    *reinterpret_cast<float4*>(&out[base + 1 * DD]) = a1;
    *reinterpret_cast<float4*>(&out[base + 2 * DD]) = a2;
    *reinterpret_cast<float4*>(&out[base + 3 * DD]) = a3;
}

// ---------------- launch ----------------
extern "C" void kernel_launch(void* const* d_in, const int* in_sizes, int n_in,
                              void* d_out, int out_size) {
    const float* x   = (const float*)d_in[0];
    const float* phi = (const float*)d_in[1];
    const float* kg  = (const float*)d_in[2];
    const float* kb  = (const float*)d_in[3];
    const float* qg  = (const float*)d_in[4];
    const float* qb  = (const float*)d_in[5];
    const float* lg  = (const float*)d_in[6];
    const float* lb  = (const float*)d_in[7];
    const float* sc  = (const float*)d_in[8];
    const float* w1  = (const float*)d_in[9];
    const float* b1  = (const float*)d_in[10];
    const float* w2  = (const float*)d_in[11];
    const float* b2  = (const float*)d_in[12];
    float* out = (float*)d_out;

    k_logits<<<dim3(32, 4), 256>>>(x, kg, kb, phi, qg, qb, lg, lb, sc);  // 1 (+qnorm +dstats)
    k_slots<<<dim3(8, 16, 4), 256>>>(x);                                 // 2
    k_red_slots<<<128, 256>>>();                                         // 3
    k_w1<<<dim3(8, 8, 32), 128>>>(w1);                                   // 4 <- ncu capture
    k_w2<<<dim3(32, 32), 256>>>(w2, b1);                                 // 5 (4-deep prefetch)
    k_red_eo<<<128, 256>>>(b2);                                          // 6
    k_combine<<<64, 256>>>(out);                                         // 7 (+scalars)
    k_out<<<dim3(8, 32, 4), 256>>>(out);                                 // 8
}

// round 14
// speedup vs baseline: 1.0985x; 1.0298x over previous
#include <cuda_runtime.h>
#include <math.h>
#include <stddef.h>

#define BB 4
#define NN 1024
#define DD 1024
#define EE 32
#define HH 4096
#define LN_EPS 1e-5f
#define PS_EPS 1e-9f

// ---------------- scratch (device globals) ----------------
__device__ __align__(16) float g_q[EE * DD];              // normalized query [e][d]
__device__ __align__(16) float g_logitsT[BB * EE * NN];   // [b][e][n]
__device__ __align__(16) float g_cw[BB * NN * EE];        // combine weights [b][n][e]
__device__ __align__(16) float2 g_minv[BB * EE];          // (max, 1/sum) per (b,e)
__device__ float g_cwterm[BB * NN];
__device__ float g_cwdiag[BB * EE];
__device__ float g_dwterm[BB * EE];
__device__ __align__(16) float g_slots_part[16][BB * EE * DD];
__device__ __align__(16) float g_slots[BB * EE * DD];
__device__ int g_cnt[64];   // [32..35] logits-batch dstats, [48] combine scalars (self-resetting)
__device__ __align__(16) float g_h1p[8][EE * BB * HH];    // pre-gelu partials (k-split 8)
__device__ __align__(16) float g_eo_part[32][BB * EE * DD];
__device__ __align__(16) float g_eo[BB * EE * DD];

__device__ __forceinline__ float fold_dq(float v) {
    v += __shfl_xor_sync(0xffffffffu, v, 8);
    v += __shfl_xor_sync(0xffffffffu, v, 16);
    return v;
}

// ---------------- K0: q = LayerNorm(phi*qg+qb)*scale (dedicated, ~2us) ----------------
__global__ __launch_bounds__(256) void k_qnorm(
    const float* __restrict__ phi, const float* __restrict__ qg,
    const float* __restrict__ qb, const float* __restrict__ lng,
    const float* __restrict__ lnb, const float* __restrict__ scale_p) {
    int e = blockIdx.x;
    int t = threadIdx.x;
    __shared__ float v[DD];
    __shared__ float red[256];

    float local = 0.f;
    for (int d = t; d < DD; d += 256) {
        float x = phi[e * DD + d] * qg[d] + qb[d];
        v[d] = x;
        local += x;
    }
    red[t] = local; __syncthreads();
    for (int s = 128; s > 0; s >>= 1) { if (t < s) red[t] += red[t + s]; __syncthreads(); }
    float mean = red[0] * (1.f / DD);
    __syncthreads();

    float lv = 0.f;
    for (int d = t; d < DD; d += 256) { float c = v[d] - mean; lv += c * c; }
    red[t] = lv; __syncthreads();
    for (int s = 128; s > 0; s >>= 1) { if (t < s) red[t] += red[t + s]; __syncthreads(); }
    float var = red[0] * (1.f / DD);
    float rstd = rsqrtf(var + LN_EPS);
    float sc = *scale_p;
    for (int d = t; d < DD; d += 256)
        g_q[e * DD + d] = ((v[d] - mean) * rstd * lng[d] + lnb[d]) * sc;
}

// ---------------- K1: logits (dstats fused via last-block-per-batch) ----------------
// grid (nt=32, b=4) = 128 blocks, 256 threads.
__global__ __launch_bounds__(256) void k_logits(
    const float* __restrict__ x, const float* __restrict__ kg,
    const float* __restrict__ kb) {
    int b = blockIdx.y;
    int n0 = blockIdx.x * 32;
    int t = threadIdx.x;
    int eq = t >> 5;         // 0..7
    int dq = (t >> 3) & 3;   // 0..3
    int nq = t & 7;          // 0..7

    __shared__ float xsT[128][36];  // [d within chunk][n]
    __shared__ float qsT[128][36];  // [d within chunk][e]
    __shared__ bool sdo;

    int w = t >> 5, l = t & 31;
    int dseg = (w & 3) * 32;        // d-segment within 128-chunk
    int half = (w >> 2) * 16;       // n-half / e-half

    float4 aN0 = make_float4(0.f, 0.f, 0.f, 0.f), aN1 = aN0, aN2 = aN0, aN3 = aN0;

    for (int c = 0; c < 8; c++) {
        int dd0 = dseg + l;              // 0..127
        int dglob = c * 128 + dd0;
        float kgv = kg[dglob], kbv = kb[dglob];
        __syncthreads();
#pragma unroll
        for (int i = 0; i < 16; i++) {
            int n = half + i;
            xsT[dd0][n] = x[((size_t)(b * NN) + n0 + n) * DD + dglob] * kgv + kbv;
            qsT[dd0][n] = g_q[n * DD + dglob];   // n doubles as expert row
        }
        __syncthreads();
#pragma unroll
        for (int k = 0; k < 32; k++) {
            int dd = dq * 32 + k;
            float4 xv = *reinterpret_cast<const float4*>(&xsT[dd][nq * 4]);
            float4 qv = *reinterpret_cast<const float4*>(&qsT[dd][eq * 4]);
            aN0.x += xv.x * qv.x; aN0.y += xv.x * qv.y; aN0.z += xv.x * qv.z; aN0.w += xv.x * qv.w;
            aN1.x += xv.y * qv.x; aN1.y += xv.y * qv.y; aN1.z += xv.y * qv.z; aN1.w += xv.y * qv.w;
            aN2.x += xv.z * qv.x; aN2.y += xv.z * qv.y; aN2.z += xv.z * qv.z; aN2.w += xv.z * qv.w;
            aN3.x += xv.w * qv.x; aN3.y += xv.w * qv.y; aN3.z += xv.w * qv.z; aN3.w += xv.w * qv.w;
        }
    }

    aN0.x = fold_dq(aN0.x); aN0.y = fold_dq(aN0.y); aN0.z = fold_dq(aN0.z); aN0.w = fold_dq(aN0.w);
    aN1.x = fold_dq(aN1.x); aN1.y = fold_dq(aN1.y); aN1.z = fold_dq(aN1.z); aN1.w = fold_dq(aN1.w);
    aN2.x = fold_dq(aN2.x); aN2.y = fold_dq(aN2.y); aN2.z = fold_dq(aN2.z); aN2.w = fold_dq(aN2.w);
    aN3.x = fold_dq(aN3.x); aN3.y = fold_dq(aN3.y); aN3.z = fold_dq(aN3.z); aN3.w = fold_dq(aN3.w);

    if (dq == 0) {
        float4 accs[4] = {aN0, aN1, aN2, aN3};
#pragma unroll
        for (int i = 0; i < 4; i++) {
            int n = n0 + nq * 4 + i;
            g_logitsT[((size_t)(b * EE) + eq * 4 + 0) * NN + n] = accs[i].x;
            g_logitsT[((size_t)(b * EE) + eq * 4 + 1) * NN + n] = accs[i].y;
            g_logitsT[((size_t)(b * EE) + eq * 4 + 2) * NN + n] = accs[i].z;
            g_logitsT[((size_t)(b * EE) + eq * 4 + 3) * NN + n] = accs[i].w;
        }
    }

    // ---- last-block dstats for this batch (reads 128 KB; cheap tail) ----
    __threadfence();
    __syncthreads();
    if (t == 0) sdo = (atomicAdd(&g_cnt[32 + b], 1) == 31);
    __syncthreads();
    if (sdo) {
        if (t == 0) g_cnt[32 + b] = 0;   // self-reset
#pragma unroll
        for (int ei = 0; ei < 4; ei++) {
            int e = w * 4 + ei;
            const float* L = g_logitsT + ((size_t)(b * EE) + e) * NN;
            float m = -1e30f;
#pragma unroll 4
            for (int k = 0; k < 32; k++) m = fmaxf(m, L[k * 32 + l]);
#pragma unroll
            for (int o = 16; o; o >>= 1) m = fmaxf(m, __shfl_xor_sync(0xffffffffu, m, o));
            float s1 = 0.f, s2 = 0.f;
#pragma unroll 4
            for (int k = 0; k < 32; k++) {
                float ex = expf(L[k * 32 + l] - m);
                s1 += ex; s2 += ex * ex;
            }
#pragma unroll
            for (int o = 16; o; o >>= 1) {
                s1 += __shfl_xor_sync(0xffffffffu, s1, o);
                s2 += __shfl_xor_sync(0xffffffffu, s2, o);
            }
            if (l == 0) {
                float inv = 1.f / s1;
                g_minv[b * EE + e] = make_float2(m, inv);
                float wsq = s2 * inv * inv;
                float rs = rsqrtf(wsq + PS_EPS);
                float rn = (s1 * inv) * rs;
                g_dwterm[b * EE + e] = rn * rn;
            }
        }
    }
}

// ---------------- K2: combine softmax (stages from logitsT) + cw metrics + fused scalars ----------------
// grid = 64 blocks, 256 threads; block covers 64 n rows of one b
__global__ __launch_bounds__(256) void k_combine(float* __restrict__ out) {
    int t = threadIdx.x;
    int w = t >> 5, l = t & 31;
    int bn0 = blockIdx.x * 64;
    int b = bn0 >> 10;
    int nb0 = bn0 & (NN - 1);
    __shared__ float cs[64][33];
    __shared__ bool sdo;

    // stage: thread t loads 8 n-values for expert e = t>>3
    {
        int e = t >> 3;
        int ng = t & 7;
        const float* L = g_logitsT + ((size_t)(b * EE) + e) * NN + nb0;
#pragma unroll
        for (int i = 0; i < 8; i++)
            cs[ng * 8 + i][e] = L[ng * 8 + i];
    }
    __syncthreads();

    int r = w * 8 + (l >> 2);
    int j = l & 3;
    float v[8];
#pragma unroll
    for (int i = 0; i < 8; i++) v[i] = cs[r][j * 8 + i];

    float m = v[0];
#pragma unroll
    for (int i = 1; i < 8; i++) m = fmaxf(m, v[i]);
    m = fmaxf(m, __shfl_xor_sync(0xffffffffu, m, 1));
    m = fmaxf(m, __shfl_xor_sync(0xffffffffu, m, 2));

    float ex[8], s = 0.f;
#pragma unroll
    for (int i = 0; i < 8; i++) { ex[i] = expf(v[i] - m); s += ex[i]; }
    s += __shfl_xor_sync(0xffffffffu, s, 1);
    s += __shfl_xor_sync(0xffffffffu, s, 2);
    float inv = 1.f / s;

    float cw[8], sq = 0.f, sc = 0.f;
#pragma unroll
    for (int i = 0; i < 8; i++) { cw[i] = ex[i] * inv; sq += cw[i] * cw[i]; sc += cw[i]; }
    sq += __shfl_xor_sync(0xffffffffu, sq, 1);
    sq += __shfl_xor_sync(0xffffffffu, sq, 2);
    sc += __shfl_xor_sync(0xffffffffu, sc, 1);
    sc += __shfl_xor_sync(0xffffffffu, sc, 2);

    int bn = bn0 + r;
    *reinterpret_cast<float4*>(&g_cw[bn * EE + j * 8]) =
        make_float4(cw[0], cw[1], cw[2], cw[3]);
    *reinterpret_cast<float4*>(&g_cw[bn * EE + j * 8 + 4]) =
        make_float4(cw[4], cw[5], cw[6], cw[7]);

    float rs = rsqrtf(sq + PS_EPS);
    float rows = sc * rs;
    int n = bn & (NN - 1);
    if (j == 0) g_cwterm[bn] = rows * rows;
    if (n < EE && j == (n >> 3))
        g_cwdiag[b * EE + n] = cw[n & 7] * rs * rows;

    // ---- last-block scalar reduction (reads ~20 KB; cheap tail) ----
    __threadfence();
    __syncthreads();
    if (t == 0) sdo = (atomicAdd(&g_cnt[48], 1) == 63);
    __syncthreads();
    if (sdo) {
        __shared__ float red[256];
        if (t == 0) g_cnt[48] = 0;   // self-reset
        float vv;

        vv = 0.f; for (int i = t; i < BB * NN; i += 256) vv += g_cwterm[i];
        red[t] = vv; __syncthreads();
        for (int st = 128; st > 0; st >>= 1) { if (t < st) red[t] += red[t + st]; __syncthreads(); }
        float sumA = red[0]; __syncthreads();

        vv = 0.f; for (int i = t; i < BB * EE; i += 256) vv += g_cwdiag[i];
        red[t] = vv; __syncthreads();
        for (int st = 128; st > 0; st >>= 1) { if (t < st) red[t] += red[t + st]; __syncthreads(); }
        float sumAd = red[0]; __syncthreads();

        vv = 0.f; for (int i = t; i < BB * EE; i += 256) vv += g_dwterm[i];
        red[t] = vv; __syncthreads();
        for (int st = 128; st > 0; st >>= 1) { if (t < st) red[t] += red[t + st]; __syncthreads(); }
        float sumB = red[0]; __syncthreads();

        vv = (t < BB) ? g_dwterm[t * EE] : 0.f;
        red[t] = vv; __syncthreads();
        for (int st = 128; st > 0; st >>= 1) { if (t < st) red[t] += red[t + st]; __syncthreads(); }
        float sumB0 = red[0];

        if (t == 0) {
            out[(size_t)BB * NN * DD]     = (sumA - sumAd) / (float)(BB * (size_t)NN * (NN - 1));
            out[(size_t)BB * NN * DD + 1] = (sumB - sumB0) / (float)(BB * EE * (EE - 1));
        }
    }
}

// ---------------- K3: slots partials ----------------
// grid (dt=8, ns=16, b=4) = 512 blocks; thread: 4e x 4d (float4), 16 accs
__global__ __launch_bounds__(256) void k_slots(const float* __restrict__ x) {
    int dt = blockIdx.x;
    int ns = blockIdx.y;
    int b = blockIdx.z;
    int t = threadIdx.x;
    int td = t & 31;   // d-quad
    int te = t >> 5;   // 0..7 -> experts te*4..te*4+3
    int d0 = dt * 128;
    int n0 = ns * 64;

    __shared__ float4 xs4[32][32];   // [nn][d-quad], 16 KB
    __shared__ float dwsT[32][33];   // [e][nn]

    float4 a0 = make_float4(0.f, 0.f, 0.f, 0.f), a1 = a0, a2 = a0, a3 = a0;

    for (int c = 0; c < 2; c++) {
        int nc = n0 + c * 32;
        __syncthreads();
        for (int i = t; i < 1024; i += 256) {
            int row = i >> 5, q = i & 31;
            xs4[row][q] = *reinterpret_cast<const float4*>(
                x + ((size_t)(b * NN) + nc + row) * DD + d0 + q * 4);
        }
        for (int i = t; i < 1024; i += 256) {
            int e = i >> 5, nn = i & 31;
            float2 mi = g_minv[b * EE + e];
            float lv = g_logitsT[((size_t)(b * EE) + e) * NN + nc + nn];
            dwsT[e][nn] = expf(lv - mi.x) * mi.y;
        }
        __syncthreads();
#pragma unroll
        for (int k = 0; k < 32; k++) {
            float4 xv = xs4[k][td];
            float w0 = dwsT[te * 4 + 0][k];
            float w1 = dwsT[te * 4 + 1][k];
            float w2 = dwsT[te * 4 + 2][k];
            float w3 = dwsT[te * 4 + 3][k];
            a0.x += w0 * xv.x; a0.y += w0 * xv.y; a0.z += w0 * xv.z; a0.w += w0 * xv.w;
            a1.x += w1 * xv.x; a1.y += w1 * xv.y; a1.z += w1 * xv.z; a1.w += w1 * xv.w;
            a2.x += w2 * xv.x; a2.y += w2 * xv.y; a2.z += w2 * xv.z; a2.w += w2 * xv.w;
            a3.x += w3 * xv.x; a3.y += w3 * xv.y; a3.z += w3 * xv.z; a3.w += w3 * xv.w;
        }
    }
    size_t base = ((size_t)(b * EE) + te * 4) * DD + d0 + td * 4;
    *reinterpret_cast<float4*>(&g_slots_part[ns][base + 0 * DD]) = a0;
    *reinterpret_cast<float4*>(&g_slots_part[ns][base + 1 * DD]) = a1;
    *reinterpret_cast<float4*>(&g_slots_part[ns][base + 2 * DD]) = a2;
    *reinterpret_cast<float4*>(&g_slots_part[ns][base + 3 * DD]) = a3;
}

// ---------------- K3b: dedicated slot-partial reduce ----------------
__global__ __launch_bounds__(256) void k_red_slots() {
    int i = blockIdx.x * 256 + threadIdx.x;  // 32768 float4s
    float4 v = reinterpret_cast<const float4*>(g_slots_part[0])[i];
#pragma unroll
    for (int p = 1; p < 16; p++) {
        float4 u = reinterpret_cast<const float4*>(g_slots_part[p])[i];
        v.x += u.x; v.y += u.y; v.z += u.z; v.w += u.w;
    }
    reinterpret_cast<float4*>(g_slots)[i] = v;
}

// ---------------- K4: w1 pass (k-split 8; proven 84us @ 82% DRAM config) ----------------
// grid (jc=8, ks=8, e=32) = 2048 blocks, 128 threads
__global__ __launch_bounds__(128) void k_w1(const float* __restrict__ w1) {
    int e = blockIdx.z;
    int ks = blockIdx.y;
    int j0 = blockIdx.x * 512 + threadIdx.x * 4;
    int d0 = ks * 128;

    __shared__ float ssp[128 * 4];  // [d][b]
    {
        int d = threadIdx.x;
#pragma unroll
        for (int bb = 0; bb < 4; bb++)
            ssp[d * 4 + bb] = g_slots[(size_t)((bb * EE) + e) * DD + d0 + d];
    }
    __syncthreads();

    const float4* ss4 = reinterpret_cast<const float4*>(ssp);
    float4 a0 = make_float4(0.f, 0.f, 0.f, 0.f), a1 = a0, a2 = a0, a3 = a0;
    const float4* wp = reinterpret_cast<const float4*>(w1 + (size_t)e * DD * HH +
                                                      (size_t)d0 * HH) + (j0 >> 2);
#pragma unroll 8
    for (int d = 0; d < 128; d++) {
        float4 wv = __ldcs(wp);
        wp += (HH / 4);
        float4 sv = ss4[d];
        a0.x += sv.x * wv.x; a0.y += sv.x * wv.y; a0.z += sv.x * wv.z; a0.w += sv.x * wv.w;
        a1.x += sv.y * wv.x; a1.y += sv.y * wv.y; a1.z += sv.y * wv.z; a1.w += sv.y * wv.w;
        a2.x += sv.z * wv.x; a2.y += sv.z * wv.y; a2.z += sv.z * wv.z; a2.w += sv.z * wv.w;
        a3.x += sv.w * wv.x; a3.y += sv.w * wv.y; a3.z += sv.w * wv.z; a3.w += sv.w * wv.w;
    }
    *reinterpret_cast<float4*>(&g_h1p[ks][(size_t)(e * 4 + 0) * HH + j0]) = a0;
    *reinterpret_cast<float4*>(&g_h1p[ks][(size_t)(e * 4 + 1) * HH + j0]) = a1;
    *reinterpret_cast<float4*>(&g_h1p[ks][(size_t)(e * 4 + 2) * HH + j0]) = a2;
    *reinterpret_cast<float4*>(&g_h1p[ks][(size_t)(e * 4 + 3) * HH + j0]) = a3;
}

// ---------------- K5: w2 pass (4-deep prefetch; proven 93.8us config) ----------------
// grid (hs=32, e=32) = 1024 blocks, 256 threads
__global__ __launch_bounds__(256) void k_w2(
    const float* __restrict__ w2, const float* __restrict__ b1) {
    int e = blockIdx.y;
    int hs = blockIdx.x;
    int h0 = hs * 128;
    int t = threadIdx.x;

    __shared__ float4 hsm4[128];  // [hh] -> (b0,b1,b2,b3)
    for (int i = t; i < 512; i += 256) {
        int b = i >> 7, hh = i & 127;
        size_t hidx = (size_t)(e * 4 + b) * HH + h0 + hh;
        float v = b1[e * HH + h0 + hh];
#pragma unroll
        for (int p = 0; p < 8; p++) v += g_h1p[p][hidx];
        v = v * normcdff(v);
        reinterpret_cast<float*>(hsm4)[hh * 4 + b] = v;
    }
    __syncthreads();

    float4 a0 = make_float4(0.f, 0.f, 0.f, 0.f), a1 = a0, a2 = a0, a3 = a0;
    const float4* wp = reinterpret_cast<const float4*>(
        w2 + (size_t)e * HH * DD + (size_t)h0 * DD) + t;

    float4 p0 = __ldcs(wp); wp += (DD / 4);
    float4 p1 = __ldcs(wp); wp += (DD / 4);
    float4 p2 = __ldcs(wp); wp += (DD / 4);
    float4 p3 = __ldcs(wp); wp += (DD / 4);

    for (int hh = 0; hh < 128; hh += 4) {
        float4 c0 = p0, c1 = p1, c2 = p2, c3 = p3;
        if (hh < 124) {
            p0 = __ldcs(wp); wp += (DD / 4);
            p1 = __ldcs(wp); wp += (DD / 4);
            p2 = __ldcs(wp); wp += (DD / 4);
            p3 = __ldcs(wp); wp += (DD / 4);
        }
        float4 h0v = hsm4[hh], h1v = hsm4[hh + 1], h2v = hsm4[hh + 2], h3v = hsm4[hh + 3];
        a0.x += h0v.x * c0.x; a0.y += h0v.x * c0.y; a0.z += h0v.x * c0.z; a0.w += h0v.x * c0.w;
        a1.x += h0v.y * c0.x; a1.y += h0v.y * c0.y; a1.z += h0v.y * c0.z; a1.w += h0v.y * c0.w;
        a2.x += h0v.z * c0.x; a2.y += h0v.z * c0.y; a2.z += h0v.z * c0.z; a2.w += h0v.z * c0.w;
        a3.x += h0v.w * c0.x; a3.y += h0v.w * c0.y; a3.z += h0v.w * c0.z; a3.w += h0v.w * c0.w;

        a0.x += h1v.x * c1.x; a0.y += h1v.x * c1.y; a0.z += h1v.x * c1.z; a0.w += h1v.x * c1.w;
        a1.x += h1v.y * c1.x; a1.y += h1v.y * c1.y; a1.z += h1v.y * c1.z; a1.w += h1v.y * c1.w;
        a2.x += h1v.z * c1.x; a2.y += h1v.z * c1.y; a2.z += h1v.z * c1.z; a2.w += h1v.z * c1.w;
        a3.x += h1v.w * c1.x; a3.y += h1v.w * c1.y; a3.z += h1v.w * c1.z; a3.w += h1v.w * c1.w;

        a0.x += h2v.x * c2.x; a0.y += h2v.x * c2.y; a0.z += h2v.x * c2.z; a0.w += h2v.x * c2.w;
        a1.x += h2v.y * c2.x; a1.y += h2v.y * c2.y; a1.z += h2v.y * c2.z; a1.w += h2v.y * c2.w;
        a2.x += h2v.z * c2.x; a2.y += h2v.z * c2.y; a2.z += h2v.z * c2.z; a2.w += h2v.z * c2.w;
        a3.x += h2v.w * c2.x; a3.y += h2v.w * c2.y; a3.z += h2v.w * c2.z; a3.w += h2v.w * c2.w;

        a0.x += h3v.x * c3.x; a0.y += h3v.x * c3.y; a0.z += h3v.x * c3.z; a0.w += h3v.x * c3.w;
        a1.x += h3v.y * c3.x; a1.y += h3v.y * c3.y; a1.z += h3v.y * c3.z; a1.w += h3v.y * c3.w;
        a2.x += h3v.z * c3.x; a2.y += h3v.z * c3.y; a2.z += h3v.z * c3.z; a2.w += h3v.z * c3.w;
        a3.x += h3v.w * c3.x; a3.y += h3v.w * c3.y; a3.z += h3v.w * c3.z; a3.w += h3v.w * c3.w;
    }

    int d0 = t * 4;
    *reinterpret_cast<float4*>(&g_eo_part[hs][((0 * EE) + e) * DD + d0]) = a0;
    *reinterpret_cast<float4*>(&g_eo_part[hs][((1 * EE) + e) * DD + d0]) = a1;
    *reinterpret_cast<float4*>(&g_eo_part[hs][((2 * EE) + e) * DD + d0]) = a2;
    *reinterpret_cast<float4*>(&g_eo_part[hs][((3 * EE) + e) * DD + d0]) = a3;
}

// ---------------- K5b: dedicated eo-partial reduce (+b2) ----------------
__global__ __launch_bounds__(256) void k_red_eo(const float* __restrict__ b2) {
    int i = blockIdx.x * 256 + threadIdx.x;  // 32768 float4s
    int e = (i >> 8) & (EE - 1);
    int dqd = i & 255;
    float4 s = reinterpret_cast<const float4*>(b2)[e * 256 + dqd];
#pragma unroll
    for (int p = 0; p < 32; p++) {
        float4 u = reinterpret_cast<const float4*>(g_eo_part[p])[i];
        s.x += u.x; s.y += u.y; s.z += u.z; s.w += u.w;
    }
    reinterpret_cast<float4*>(g_eo)[i] = s;
}

// ---------------- K6: out (register micro-tile GEMM over e) ----------------
// grid (dt=8, nt=32, b=4) = 1024 blocks; thread: 4n x 4d (float4)
__global__ __launch_bounds__(256) void k_out(float* __restrict__ out) {
    int dt = blockIdx.x;
    int nt = blockIdx.y;
    int b = blockIdx.z;
    int t = threadIdx.x;
    int td = t & 31;
    int tn = t >> 5;   // 0..7 -> rows tn*4..tn*4+3
    int d0 = dt * 128;
    int n0 = nt * 32;

    __shared__ float4 eos4[32][32];  // [e][d-quad], 16 KB
    __shared__ float cwTs[32][33];   // [e][nn]

    for (int i = t; i < 1024; i += 256) {
        int e = i >> 5, q = i & 31;
        eos4[e][q] = *reinterpret_cast<const float4*>(
            &g_eo[((b * EE) + e) * DD + d0 + q * 4]);
    }
    {
        int nn = t >> 3, equad = t & 7;
        float4 v = *reinterpret_cast<const float4*>(
            &g_cw[((size_t)(b * NN) + n0 + nn) * EE + equad * 4]);
        cwTs[equad * 4 + 0][nn] = v.x;
        cwTs[equad * 4 + 1][nn] = v.y;
        cwTs[equad * 4 + 2][nn] = v.z;
        cwTs[equad * 4 + 3][nn] = v.w;
    }
    __syncthreads();

    float4 a0 = make_float4(0.f, 0.f, 0.f, 0.f), a1 = a0, a2 = a0, a3 = a0;
#pragma unroll
    for (int e = 0; e < 32; e++) {
        float4 ev = eos4[e][td];
        float c0 = cwTs[e][tn * 4 + 0];
        float c1 = cwTs[e][tn * 4 + 1];
        float c2 = cwTs[e][tn * 4 + 2];
        float c3 = cwTs[e][tn * 4 + 3];
        a0.x += c0 * ev.x; a0.y += c0 * ev.y; a0.z += c0 * ev.z; a0.w += c0 * ev.w;
        a1.x += c1 * ev.x; a1.y += c1 * ev.y; a1.z += c1 * ev.z; a1.w += c1 * ev.w;
        a2.x += c2 * ev.x; a2.y += c2 * ev.y; a2.z += c2 * ev.z; a2.w += c2 * ev.w;
        a3.x += c3 * ev.x; a3.y += c3 * ev.y; a3.z += c3 * ev.z; a3.w += c3 * ev.w;
    }
    size_t base = ((size_t)(b * NN) + n0 + tn * 4) * DD + d0 + td * 4;
    *reinterpret_cast<float4*>(&out[base + 0 * DD]) = a0;
    *reinterpret_cast<float4*>(&out[base + 1 * DD]) = a1;
    *reinterpret_cast<float4*>(&out[base + 2 * DD]) = a2;
    *reinterpret_cast<float4*>(&out[base + 3 * DD]) = a3;
}

// ---------------- launch ----------------
extern "C" void kernel_launch(void* const* d_in, const int* in_sizes, int n_in,
                              void* d_out, int out_size) {
    const float* x   = (const float*)d_in[0];
    const float* phi = (const float*)d_in[1];
    const float* kg  = (const float*)d_in[2];
    const float* kb  = (const float*)d_in[3];
    const float* qg  = (const float*)d_in[4];
    const float* qb  = (const float*)d_in[5];
    const float* lg  = (const float*)d_in[6];
    const float* lb  = (const float*)d_in[7];
    const float* sc  = (const float*)d_in[8];
    const float* w1  = (const float*)d_in[9];
    const float* b1  = (const float*)d_in[10];
    const float* w2  = (const float*)d_in[11];
    const float* b2  = (const float*)d_in[12];
    float* out = (float*)d_out;

    k_qnorm<<<EE, 256>>>(phi, qg, qb, lg, lb, sc);        // 1
    k_logits<<<dim3(32, 4), 256>>>(x, kg, kb);            // 2 (+dstats)
    k_combine<<<64, 256>>>(out);                          // 3 (+scalars)
    k_slots<<<dim3(8, 16, 4), 256>>>(x);                  // 4 <- ncu capture (variance probe)
    k_red_slots<<<128, 256>>>();                          // 5
    k_w1<<<dim3(8, 8, 32), 128>>>(w1);                    // 6
    k_w2<<<dim3(32, 32), 256>>>(w2, b1);                  // 7
    k_red_eo<<<128, 256>>>(b2);                           // 8
    k_out<<<dim3(8, 32, 4), 256>>>(out);                  // 9
}

// round 15
// speedup vs baseline: 1.2889x; 1.1733x over previous
#include <cuda_runtime.h>
#include <math.h>
#include <stddef.h>

#define BB 4
#define NN 1024
#define DD 1024
#define EE 32
#define HH 4096
#define LN_EPS 1e-5f
#define PS_EPS 1e-9f

// ---------------- scratch (device globals) ----------------
__device__ __align__(16) float g_q[EE * DD];              // normalized query [e][d]
__device__ __align__(16) float g_logp[4][BB * EE * NN];   // logits D-split partials
__device__ __align__(16) float g_logitsT[BB * EE * NN];   // [b][e][n]
__device__ __align__(16) float g_cw[BB * NN * EE];        // combine weights [b][n][e]
__device__ __align__(16) float2 g_minv[BB * EE];          // (max, 1/sum) per (b,e)
__device__ float g_cwterm[BB * NN];
__device__ float g_cwdiag[BB * EE];
__device__ float g_dwterm[BB * EE];
__device__ __align__(16) float g_slots_part[16][BB * EE * DD];
__device__ __align__(16) float g_slots[BB * EE * DD];
__device__ int g_cnt[64];   // [48] combine scalars (self-resetting)
__device__ __align__(16) float g_h1p[8][EE * BB * HH];    // pre-gelu partials (k-split 8)
__device__ __align__(16) float g_eo_part[32][BB * EE * DD];
__device__ __align__(16) float g_eo[BB * EE * DD];

__device__ __forceinline__ float fold_dq(float v) {
    v += __shfl_xor_sync(0xffffffffu, v, 8);
    v += __shfl_xor_sync(0xffffffffu, v, 16);
    return v;
}

// ---------------- K0: q = LayerNorm(phi*qg+qb)*scale ----------------
__global__ __launch_bounds__(256) void k_qnorm(
    const float* __restrict__ phi, const float* __restrict__ qg,
    const float* __restrict__ qb, const float* __restrict__ lng,
    const float* __restrict__ lnb, const float* __restrict__ scale_p) {
    int e = blockIdx.x;
    int t = threadIdx.x;
    __shared__ float v[DD];
    __shared__ float red[256];

    float local = 0.f;
    for (int d = t; d < DD; d += 256) {
        float x = phi[e * DD + d] * qg[d] + qb[d];
        v[d] = x;
        local += x;
    }
    red[t] = local; __syncthreads();
    for (int s = 128; s > 0; s >>= 1) { if (t < s) red[t] += red[t + s]; __syncthreads(); }
    float mean = red[0] * (1.f / DD);
    __syncthreads();

    float lv = 0.f;
    for (int d = t; d < DD; d += 256) { float c = v[d] - mean; lv += c * c; }
    red[t] = lv; __syncthreads();
    for (int s = 128; s > 0; s >>= 1) { if (t < s) red[t] += red[t + s]; __syncthreads(); }
    float var = red[0] * (1.f / DD);
    float rstd = rsqrtf(var + LN_EPS);
    float sc = *scale_p;
    for (int d = t; d < DD; d += 256)
        g_q[e * DD + d] = ((v[d] - mean) * rstd * lng[d] + lnb[d]) * sc;
}

// ---------------- K1: logits D-split partials ----------------
// grid (nt=32, ds=4, b=4) = 512 blocks, 256 threads; block covers d in [ds*256, ds*256+256)
__global__ __launch_bounds__(256) void k_logits_part(
    const float* __restrict__ x, const float* __restrict__ kg,
    const float* __restrict__ kb) {
    int nt = blockIdx.x;
    int ds = blockIdx.y;
    int b = blockIdx.z;
    int n0 = nt * 32;
    int t = threadIdx.x;
    int eq = t >> 5;         // 0..7
    int dq = (t >> 3) & 3;   // 0..3
    int nq = t & 7;          // 0..7

    __shared__ float xsT[128][36];  // [d within chunk][n]
    __shared__ float qsT[128][36];  // [d within chunk][e]

    int w = t >> 5, l = t & 31;
    int dseg = (w & 3) * 32;        // d-segment within 128-chunk
    int half = (w >> 2) * 16;       // n-half / e-half

    float4 aN0 = make_float4(0.f, 0.f, 0.f, 0.f), aN1 = aN0, aN2 = aN0, aN3 = aN0;

    for (int c = 0; c < 2; c++) {
        int dd0 = dseg + l;              // 0..127
        int dglob = ds * 256 + c * 128 + dd0;
        float kgv = kg[dglob], kbv = kb[dglob];
        __syncthreads();
#pragma unroll
        for (int i = 0; i < 16; i++) {
            int n = half + i;
            xsT[dd0][n] = x[((size_t)(b * NN) + n0 + n) * DD + dglob] * kgv + kbv;
            qsT[dd0][n] = g_q[n * DD + dglob];   // n doubles as expert row
        }
        __syncthreads();
#pragma unroll
        for (int k = 0; k < 32; k++) {
            int dd = dq * 32 + k;
            float4 xv = *reinterpret_cast<const float4*>(&xsT[dd][nq * 4]);
            float4 qv = *reinterpret_cast<const float4*>(&qsT[dd][eq * 4]);
            aN0.x += xv.x * qv.x; aN0.y += xv.x * qv.y; aN0.z += xv.x * qv.z; aN0.w += xv.x * qv.w;
            aN1.x += xv.y * qv.x; aN1.y += xv.y * qv.y; aN1.z += xv.y * qv.z; aN1.w += xv.y * qv.w;
            aN2.x += xv.z * qv.x; aN2.y += xv.z * qv.y; aN2.z += xv.z * qv.z; aN2.w += xv.z * qv.w;
            aN3.x += xv.w * qv.x; aN3.y += xv.w * qv.y; aN3.z += xv.w * qv.z; aN3.w += xv.w * qv.w;
        }
    }

    aN0.x = fold_dq(aN0.x); aN0.y = fold_dq(aN0.y); aN0.z = fold_dq(aN0.z); aN0.w = fold_dq(aN0.w);
    aN1.x = fold_dq(aN1.x); aN1.y = fold_dq(aN1.y); aN1.z = fold_dq(aN1.z); aN1.w = fold_dq(aN1.w);
    aN2.x = fold_dq(aN2.x); aN2.y = fold_dq(aN2.y); aN2.z = fold_dq(aN2.z); aN2.w = fold_dq(aN2.w);
    aN3.x = fold_dq(aN3.x); aN3.y = fold_dq(aN3.y); aN3.z = fold_dq(aN3.z); aN3.w = fold_dq(aN3.w);

    if (dq == 0) {
        float4 accs[4] = {aN0, aN1, aN2, aN3};
#pragma unroll
        for (int i = 0; i < 4; i++) {
            int n = n0 + nq * 4 + i;
            g_logp[ds][((size_t)(b * EE) + eq * 4 + 0) * NN + n] = accs[i].x;
            g_logp[ds][((size_t)(b * EE) + eq * 4 + 1) * NN + n] = accs[i].y;
            g_logp[ds][((size_t)(b * EE) + eq * 4 + 2) * NN + n] = accs[i].z;
            g_logp[ds][((size_t)(b * EE) + eq * 4 + 3) * NN + n] = accs[i].w;
        }
    }
}

// ---------------- K1b: reduce logit partials + dispatch stats + dw metric ----------------
// grid = BB*EE = 128 blocks (one per (b,e) row), 256 threads
__global__ __launch_bounds__(256) void k_red_logits() {
    int be = blockIdx.x;
    int t = threadIdx.x;
    __shared__ float red[256];

    float4 v = reinterpret_cast<const float4*>(g_logp[0])[be * 256 + t];
#pragma unroll
    for (int p = 1; p < 4; p++) {
        float4 u = reinterpret_cast<const float4*>(g_logp[p])[be * 256 + t];
        v.x += u.x; v.y += u.y; v.z += u.z; v.w += u.w;
    }
    reinterpret_cast<float4*>(g_logitsT)[be * 256 + t] = v;

    float m = fmaxf(fmaxf(v.x, v.y), fmaxf(v.z, v.w));
    red[t] = m; __syncthreads();
    for (int s = 128; s > 0; s >>= 1) { if (t < s) red[t] = fmaxf(red[t], red[t + s]); __syncthreads(); }
    m = red[0]; __syncthreads();

    float ex0 = expf(v.x - m), ex1 = expf(v.y - m), ex2 = expf(v.z - m), ex3 = expf(v.w - m);
    red[t] = ex0 + ex1 + ex2 + ex3; __syncthreads();
    for (int s = 128; s > 0; s >>= 1) { if (t < s) red[t] += red[t + s]; __syncthreads(); }
    float s1 = red[0]; __syncthreads();

    red[t] = ex0 * ex0 + ex1 * ex1 + ex2 * ex2 + ex3 * ex3; __syncthreads();
    for (int s = 128; s > 0; s >>= 1) { if (t < s) red[t] += red[t + s]; __syncthreads(); }

    if (t == 0) {
        float s2 = red[0];
        float inv = 1.f / s1;
        g_minv[be] = make_float2(m, inv);
        float wsq = s2 * inv * inv;
        float rs = rsqrtf(wsq + PS_EPS);
        float rn = (s1 * inv) * rs;
        g_dwterm[be] = rn * rn;
    }
}

// ---------------- K2: combine softmax (stages from logitsT) + cw metrics + fused scalars ----------------
// grid = 64 blocks, 256 threads; block covers 64 n rows of one b
__global__ __launch_bounds__(256) void k_combine(float* __restrict__ out) {
    int t = threadIdx.x;
    int w = t >> 5, l = t & 31;
    int bn0 = blockIdx.x * 64;
    int b = bn0 >> 10;
    int nb0 = bn0 & (NN - 1);
    __shared__ float cs[64][33];
    __shared__ bool sdo;

    // stage: thread t loads 8 n-values for expert e = t>>3
    {
        int e = t >> 3;
        int ng = t & 7;
        const float* L = g_logitsT + ((size_t)(b * EE) + e) * NN + nb0;
#pragma unroll
        for (int i = 0; i < 8; i++)
            cs[ng * 8 + i][e] = L[ng * 8 + i];
    }
    __syncthreads();

    int r = w * 8 + (l >> 2);
    int j = l & 3;
    float v[8];
#pragma unroll
    for (int i = 0; i < 8; i++) v[i] = cs[r][j * 8 + i];

    float m = v[0];
#pragma unroll
    for (int i = 1; i < 8; i++) m = fmaxf(m, v[i]);
    m = fmaxf(m, __shfl_xor_sync(0xffffffffu, m, 1));
    m = fmaxf(m, __shfl_xor_sync(0xffffffffu, m, 2));

    float ex[8], s = 0.f;
#pragma unroll
    for (int i = 0; i < 8; i++) { ex[i] = expf(v[i] - m); s += ex[i]; }
    s += __shfl_xor_sync(0xffffffffu, s, 1);
    s += __shfl_xor_sync(0xffffffffu, s, 2);
    float inv = 1.f / s;

    float cw[8], sq = 0.f, sc = 0.f;
#pragma unroll
    for (int i = 0; i < 8; i++) { cw[i] = ex[i] * inv; sq += cw[i] * cw[i]; sc += cw[i]; }
    sq += __shfl_xor_sync(0xffffffffu, sq, 1);
    sq += __shfl_xor_sync(0xffffffffu, sq, 2);
    sc += __shfl_xor_sync(0xffffffffu, sc, 1);
    sc += __shfl_xor_sync(0xffffffffu, sc, 2);

    int bn = bn0 + r;
    *reinterpret_cast<float4*>(&g_cw[bn * EE + j * 8]) =
        make_float4(cw[0], cw[1], cw[2], cw[3]);
    *reinterpret_cast<float4*>(&g_cw[bn * EE + j * 8 + 4]) =
        make_float4(cw[4], cw[5], cw[6], cw[7]);

    float rs = rsqrtf(sq + PS_EPS);
    float rows = sc * rs;
    int n = bn & (NN - 1);
    if (j == 0) g_cwterm[bn] = rows * rows;
    if (n < EE && j == (n >> 3))
        g_cwdiag[b * EE + n] = cw[n & 7] * rs * rows;

    // ---- last-block scalar reduction (reads ~20 KB; cheap tail) ----
    __threadfence();
    __syncthreads();
    if (t == 0) sdo = (atomicAdd(&g_cnt[48], 1) == 63);
    __syncthreads();
    if (sdo) {
        __shared__ float red[256];
        if (t == 0) g_cnt[48] = 0;   // self-reset
        float vv;

        vv = 0.f; for (int i = t; i < BB * NN; i += 256) vv += g_cwterm[i];
        red[t] = vv; __syncthreads();
        for (int st = 128; st > 0; st >>= 1) { if (t < st) red[t] += red[t + st]; __syncthreads(); }
        float sumA = red[0]; __syncthreads();

        vv = 0.f; for (int i = t; i < BB * EE; i += 256) vv += g_cwdiag[i];
        red[t] = vv; __syncthreads();
        for (int st = 128; st > 0; st >>= 1) { if (t < st) red[t] += red[t + st]; __syncthreads(); }
        float sumAd = red[0]; __syncthreads();

        vv = 0.f; for (int i = t; i < BB * EE; i += 256) vv += g_dwterm[i];
        red[t] = vv; __syncthreads();
        for (int st = 128; st > 0; st >>= 1) { if (t < st) red[t] += red[t + st]; __syncthreads(); }
        float sumB = red[0]; __syncthreads();

        vv = (t < BB) ? g_dwterm[t * EE] : 0.f;
        red[t] = vv; __syncthreads();
        for (int st = 128; st > 0; st >>= 1) { if (t < st) red[t] += red[t + st]; __syncthreads(); }
        float sumB0 = red[0];

        if (t == 0) {
            out[(size_t)BB * NN * DD]     = (sumA - sumAd) / (float)(BB * (size_t)NN * (NN - 1));
            out[(size_t)BB * NN * DD + 1] = (sumB - sumB0) / (float)(BB * EE * (EE - 1));
        }
    }
}

// ---------------- K3: slots partials ----------------
// grid (dt=8, ns=16, b=4) = 512 blocks; thread: 4e x 4d (float4), 16 accs
__global__ __launch_bounds__(256) void k_slots(const float* __restrict__ x) {
    int dt = blockIdx.x;
    int ns = blockIdx.y;
    int b = blockIdx.z;
    int t = threadIdx.x;
    int td = t & 31;   // d-quad
    int te = t >> 5;   // 0..7 -> experts te*4..te*4+3
    int d0 = dt * 128;
    int n0 = ns * 64;

    __shared__ float4 xs4[32][32];   // [nn][d-quad], 16 KB
    __shared__ float dwsT[32][33];   // [e][nn]

    float4 a0 = make_float4(0.f, 0.f, 0.f, 0.f), a1 = a0, a2 = a0, a3 = a0;

    for (int c = 0; c < 2; c++) {
        int nc = n0 + c * 32;
        __syncthreads();
        for (int i = t; i < 1024; i += 256) {
            int row = i >> 5, q = i & 31;
            xs4[row][q] = *reinterpret_cast<const float4*>(
                x + ((size_t)(b * NN) + nc + row) * DD + d0 + q * 4);
        }
        for (int i = t; i < 1024; i += 256) {
            int e = i >> 5, nn = i & 31;
            float2 mi = g_minv[b * EE + e];
            float lv = g_logitsT[((size_t)(b * EE) + e) * NN + nc + nn];
            dwsT[e][nn] = expf(lv - mi.x) * mi.y;
        }
        __syncthreads();
#pragma unroll
        for (int k = 0; k < 32; k++) {
            float4 xv = xs4[k][td];
            float w0 = dwsT[te * 4 + 0][k];
            float w1 = dwsT[te * 4 + 1][k];
            float w2 = dwsT[te * 4 + 2][k];
            float w3 = dwsT[te * 4 + 3][k];
            a0.x += w0 * xv.x; a0.y += w0 * xv.y; a0.z += w0 * xv.z; a0.w += w0 * xv.w;
            a1.x += w1 * xv.x; a1.y += w1 * xv.y; a1.z += w1 * xv.z; a1.w += w1 * xv.w;
            a2.x += w2 * xv.x; a2.y += w2 * xv.y; a2.z += w2 * xv.z; a2.w += w2 * xv.w;
            a3.x += w3 * xv.x; a3.y += w3 * xv.y; a3.z += w3 * xv.z; a3.w += w3 * xv.w;
        }
    }
    size_t base = ((size_t)(b * EE) + te * 4) * DD + d0 + td * 4;
    *reinterpret_cast<float4*>(&g_slots_part[ns][base + 0 * DD]) = a0;
    *reinterpret_cast<float4*>(&g_slots_part[ns][base + 1 * DD]) = a1;
    *reinterpret_cast<float4*>(&g_slots_part[ns][base + 2 * DD]) = a2;
    *reinterpret_cast<float4*>(&g_slots_part[ns][base + 3 * DD]) = a3;
}

// ---------------- K3b: dedicated slot-partial reduce ----------------
__global__ __launch_bounds__(256) void k_red_slots() {
    int i = blockIdx.x * 256 + threadIdx.x;  // 32768 float4s
    float4 v = reinterpret_cast<const float4*>(g_slots_part[0])[i];
#pragma unroll
    for (int p = 1; p < 16; p++) {
        float4 u = reinterpret_cast<const float4*>(g_slots_part[p])[i];
        v.x += u.x; v.y += u.y; v.z += u.z; v.w += u.w;
    }
    reinterpret_cast<float4*>(g_slots)[i] = v;
}

// ---------------- K4: w1 pass (k-split 8; proven 84us @ 82% DRAM config) ----------------
// grid (jc=8, ks=8, e=32) = 2048 blocks, 128 threads
__global__ __launch_bounds__(128) void k_w1(const float* __restrict__ w1) {
    int e = blockIdx.z;
    int ks = blockIdx.y;
    int j0 = blockIdx.x * 512 + threadIdx.x * 4;
    int d0 = ks * 128;

    __shared__ float ssp[128 * 4];  // [d][b]
    {
        int d = threadIdx.x;
#pragma unroll
        for (int bb = 0; bb < 4; bb++)
            ssp[d * 4 + bb] = g_slots[(size_t)((bb * EE) + e) * DD + d0 + d];
    }
    __syncthreads();

    const float4* ss4 = reinterpret_cast<const float4*>(ssp);
    float4 a0 = make_float4(0.f, 0.f, 0.f, 0.f), a1 = a0, a2 = a0, a3 = a0;
    const float4* wp = reinterpret_cast<const float4*>(w1 + (size_t)e * DD * HH +
                                                      (size_t)d0 * HH) + (j0 >> 2);
#pragma unroll 8
    for (int d = 0; d < 128; d++) {
        float4 wv = __ldcs(wp);
        wp += (HH / 4);
        float4 sv = ss4[d];
        a0.x += sv.x * wv.x; a0.y += sv.x * wv.y; a0.z += sv.x * wv.z; a0.w += sv.x * wv.w;
        a1.x += sv.y * wv.x; a1.y += sv.y * wv.y; a1.z += sv.y * wv.z; a1.w += sv.y * wv.w;
        a2.x += sv.z * wv.x; a2.y += sv.z * wv.y; a2.z += sv.z * wv.z; a2.w += sv.z * wv.w;
        a3.x += sv.w * wv.x; a3.y += sv.w * wv.y; a3.z += sv.w * wv.z; a3.w += sv.w * wv.w;
    }
    *reinterpret_cast<float4*>(&g_h1p[ks][(size_t)(e * 4 + 0) * HH + j0]) = a0;
    *reinterpret_cast<float4*>(&g_h1p[ks][(size_t)(e * 4 + 1) * HH + j0]) = a1;
    *reinterpret_cast<float4*>(&g_h1p[ks][(size_t)(e * 4 + 2) * HH + j0]) = a2;
    *reinterpret_cast<float4*>(&g_h1p[ks][(size_t)(e * 4 + 3) * HH + j0]) = a3;
}

// ---------------- K5: w2 pass (4-deep prefetch; proven 93.8us config) ----------------
// grid (hs=32, e=32) = 1024 blocks, 256 threads
__global__ __launch_bounds__(256) void k_w2(
    const float* __restrict__ w2, const float* __restrict__ b1) {
    int e = blockIdx.y;
    int hs = blockIdx.x;
    int h0 = hs * 128;
    int t = threadIdx.x;

    __shared__ float4 hsm4[128];  // [hh] -> (b0,b1,b2,b3)
    for (int i = t; i < 512; i += 256) {
        int b = i >> 7, hh = i & 127;
        size_t hidx = (size_t)(e * 4 + b) * HH + h0 + hh;
        float v = b1[e * HH + h0 + hh];
#pragma unroll
        for (int p = 0; p < 8; p++) v += g_h1p[p][hidx];
        v = v * normcdff(v);
        reinterpret_cast<float*>(hsm4)[hh * 4 + b] = v;
    }
    __syncthreads();

    float4 a0 = make_float4(0.f, 0.f, 0.f, 0.f), a1 = a0, a2 = a0, a3 = a0;
    const float4* wp = reinterpret_cast<const float4*>(
        w2 + (size_t)e * HH * DD + (size_t)h0 * DD) + t;

    float4 p0 = __ldcs(wp); wp += (DD / 4);
    float4 p1 = __ldcs(wp); wp += (DD / 4);
    float4 p2 = __ldcs(wp); wp += (DD / 4);
    float4 p3 = __ldcs(wp); wp += (DD / 4);

    for (int hh = 0; hh < 128; hh += 4) {
        float4 c0 = p0, c1 = p1, c2 = p2, c3 = p3;
        if (hh < 124) {
            p0 = __ldcs(wp); wp += (DD / 4);
            p1 = __ldcs(wp); wp += (DD / 4);
            p2 = __ldcs(wp); wp += (DD / 4);
            p3 = __ldcs(wp); wp += (DD / 4);
        }
        float4 h0v = hsm4[hh], h1v = hsm4[hh + 1], h2v = hsm4[hh + 2], h3v = hsm4[hh + 3];
        a0.x += h0v.x * c0.x; a0.y += h0v.x * c0.y; a0.z += h0v.x * c0.z; a0.w += h0v.x * c0.w;
        a1.x += h0v.y * c0.x; a1.y += h0v.y * c0.y; a1.z += h0v.y * c0.z; a1.w += h0v.y * c0.w;
        a2.x += h0v.z * c0.x; a2.y += h0v.z * c0.y; a2.z += h0v.z * c0.z; a2.w += h0v.z * c0.w;
        a3.x += h0v.w * c0.x; a3.y += h0v.w * c0.y; a3.z += h0v.w * c0.z; a3.w += h0v.w * c0.w;

        a0.x += h1v.x * c1.x; a0.y += h1v.x * c1.y; a0.z += h1v.x * c1.z; a0.w += h1v.x * c1.w;
        a1.x += h1v.y * c1.x; a1.y += h1v.y * c1.y; a1.z += h1v.y * c1.z; a1.w += h1v.y * c1.w;
        a2.x += h1v.z * c1.x; a2.y += h1v.z * c1.y; a2.z += h1v.z * c1.z; a2.w += h1v.z * c1.w;
        a3.x += h1v.w * c1.x; a3.y += h1v.w * c1.y; a3.z += h1v.w * c1.z; a3.w += h1v.w * c1.w;

        a0.x += h2v.x * c2.x; a0.y += h2v.x * c2.y; a0.z += h2v.x * c2.z; a0.w += h2v.x * c2.w;
        a1.x += h2v.y * c2.x; a1.y += h2v.y * c2.y; a1.z += h2v.y * c2.z; a1.w += h2v.y * c2.w;
        a2.x += h2v.z * c2.x; a2.y += h2v.z * c2.y; a2.z += h2v.z * c2.z; a2.w += h2v.z * c2.w;
        a3.x += h2v.w * c2.x; a3.y += h2v.w * c2.y; a3.z += h2v.w * c2.z; a3.w += h2v.w * c2.w;

        a0.x += h3v.x * c3.x; a0.y += h3v.x * c3.y; a0.z += h3v.x * c3.z; a0.w += h3v.x * c3.w;
        a1.x += h3v.y * c3.x; a1.y += h3v.y * c3.y; a1.z += h3v.y * c3.z; a1.w += h3v.y * c3.w;
        a2.x += h3v.z * c3.x; a2.y += h3v.z * c3.y; a2.z += h3v.z * c3.z; a2.w += h3v.z * c3.w;
        a3.x += h3v.w * c3.x; a3.y += h3v.w * c3.y; a3.z += h3v.w * c3.z; a3.w += h3v.w * c3.w;
    }

    int d0 = t * 4;
    *reinterpret_cast<float4*>(&g_eo_part[hs][((0 * EE) + e) * DD + d0]) = a0;
    *reinterpret_cast<float4*>(&g_eo_part[hs][((1 * EE) + e) * DD + d0]) = a1;
    *reinterpret_cast<float4*>(&g_eo_part[hs][((2 * EE) + e) * DD + d0]) = a2;
    *reinterpret_cast<float4*>(&g_eo_part[hs][((3 * EE) + e) * DD + d0]) = a3;
}

// ---------------- K5b: dedicated eo-partial reduce (+b2) ----------------
__global__ __launch_bounds__(256) void k_red_eo(const float* __restrict__ b2) {
    int i = blockIdx.x * 256 + threadIdx.x;  // 32768 float4s
    int e = (i >> 8) & (EE - 1);
    int dqd = i & 255;
    float4 s = reinterpret_cast<const float4*>(b2)[e * 256 + dqd];
#pragma unroll
    for (int p = 0; p < 32; p++) {
        float4 u = reinterpret_cast<const float4*>(g_eo_part[p])[i];
        s.x += u.x; s.y += u.y; s.z += u.z; s.w += u.w;
    }
    reinterpret_cast<float4*>(g_eo)[i] = s;
}

// ---------------- K6: out (register micro-tile GEMM over e) ----------------
// grid (dt=8, nt=32, b=4) = 1024 blocks; thread: 4n x 4d (float4)
__global__ __launch_bounds__(256) void k_out(float* __restrict__ out) {
    int dt = blockIdx.x;
    int nt = blockIdx.y;
    int b = blockIdx.z;
    int t = threadIdx.x;
    int td = t & 31;
    int tn = t >> 5;   // 0..7 -> rows tn*4..tn*4+3
    int d0 = dt * 128;
    int n0 = nt * 32;

    __shared__ float4 eos4[32][32];  // [e][d-quad], 16 KB
    __shared__ float cwTs[32][33];   // [e][nn]

    for (int i = t; i < 1024; i += 256) {
        int e = i >> 5, q = i & 31;
        eos4[e][q] = *reinterpret_cast<const float4*>(
            &g_eo[((b * EE) + e) * DD + d0 + q * 4]);
    }
    {
        int nn = t >> 3, equad = t & 7;
        float4 v = *reinterpret_cast<const float4*>(
            &g_cw[((size_t)(b * NN) + n0 + nn) * EE + equad * 4]);
        cwTs[equad * 4 + 0][nn] = v.x;
        cwTs[equad * 4 + 1][nn] = v.y;
        cwTs[equad * 4 + 2][nn] = v.z;
        cwTs[equad * 4 + 3][nn] = v.w;
    }
    __syncthreads();

    float4 a0 = make_float4(0.f, 0.f, 0.f, 0.f), a1 = a0, a2 = a0, a3 = a0;
#pragma unroll
    for (int e = 0; e < 32; e++) {
        float4 ev = eos4[e][td];
        float c0 = cwTs[e][tn * 4 + 0];
        float c1 = cwTs[e][tn * 4 + 1];
        float c2 = cwTs[e][tn * 4 + 2];
        float c3 = cwTs[e][tn * 4 + 3];
        a0.x += c0 * ev.x; a0.y += c0 * ev.y; a0.z += c0 * ev.z; a0.w += c0 * ev.w;
        a1.x += c1 * ev.x; a1.y += c1 * ev.y; a1.z += c1 * ev.z; a1.w += c1 * ev.w;
        a2.x += c2 * ev.x; a2.y += c2 * ev.y; a2.z += c2 * ev.z; a2.w += c2 * ev.w;
        a3.x += c3 * ev.x; a3.y += c3 * ev.y; a3.z += c3 * ev.z; a3.w += c3 * ev.w;
    }
    size_t base = ((size_t)(b * NN) + n0 + tn * 4) * DD + d0 + td * 4;
    *reinterpret_cast<float4*>(&out[base + 0 * DD]) = a0;
    *reinterpret_cast<float4*>(&out[base + 1 * DD]) = a1;
    *reinterpret_cast<float4*>(&out[base + 2 * DD]) = a2;
    *reinterpret_cast<float4*>(&out[base + 3 * DD]) = a3;
}

// ---------------- launch ----------------
extern "C" void kernel_launch(void* const* d_in, const int* in_sizes, int n_in,
                              void* d_out, int out_size) {
    const float* x   = (const float*)d_in[0];
    const float* phi = (const float*)d_in[1];
    const float* kg  = (const float*)d_in[2];
    const float* kb  = (const float*)d_in[3];
    const float* qg  = (const float*)d_in[4];
    const float* qb  = (const float*)d_in[5];
    const float* lg  = (const float*)d_in[6];
    const float* lb  = (const float*)d_in[7];
    const float* sc  = (const float*)d_in[8];
    const float* w1  = (const float*)d_in[9];
    const float* b1  = (const float*)d_in[10];
    const float* w2  = (const float*)d_in[11];
    const float* b2  = (const float*)d_in[12];
    float* out = (float*)d_out;

    k_qnorm<<<EE, 256>>>(phi, qg, qb, lg, lb, sc);         // 1
    k_logits_part<<<dim3(32, 4, 4), 256>>>(x, kg, kb);     // 2 (512 blocks)
    k_red_logits<<<BB * EE, 256>>>();                      // 3 (+dstats)
    k_combine<<<64, 256>>>(out);                           // 4 <- ncu capture (+scalars)
    k_slots<<<dim3(8, 16, 4), 256>>>(x);                   // 5
    k_red_slots<<<128, 256>>>();                           // 6
    k_w1<<<dim3(8, 8, 32), 128>>>(w1);                     // 7
    k_w2<<<dim3(32, 32), 256>>>(w2, b1);                   // 8
    k_red_eo<<<128, 256>>>(b2);                            // 9
    k_out<<<dim3(8, 32, 4), 256>>>(out);                   // 10
}